// round 2
// baseline (speedup 1.0000x reference)
#include <cuda_runtime.h>
#include <math.h>

// Problem constants
#define D_MODEL 1024
#define S_LEN   2048
#define BATCH   4
#define NHEAD   16
#define HDIM    64
#define MROWS   (BATCH * S_LEN)   // 8192

// -------------------- scratch (device globals; no allocation allowed) ------
__device__ float g_Qp[MROWS * D_MODEL];   // projected Q  [B,S,D]
__device__ float g_Kp[MROWS * D_MODEL];   // projected K
__device__ float g_Vp[MROWS * D_MODEL];   // projected V
__device__ float g_At[MROWS * D_MODEL];   // attention output (heads concat)

// dst selector: 0 -> g_Qp, 1 -> g_Kp, 2 -> g_Vp, 3 -> external (Cout)
__device__ __forceinline__ float* gemm_dst(int sel, float* Cout) {
    switch (sel) {
        case 0: return g_Qp;
        case 1: return g_Kp;
        case 2: return g_Vp;
        default: return Cout;
    }
}
// src selector: 0 -> external (Ain), 1 -> g_At
__device__ __forceinline__ const float* gemm_src(int sel, const float* Ain) {
    return (sel == 1) ? g_At : Ain;
}

// ============================================================================
// SGEMM: C[M,N] = A[M,K] @ W[K,N] + bias[N]     (M=8192, N=K=1024)
// 128x128 block tile, BK=16, 256 threads, 8x8 per-thread microtile.
// ============================================================================
__global__ void __launch_bounds__(256) sgemm_bias_kernel(
    const float* __restrict__ Ain, const float* __restrict__ W,
    const float* __restrict__ bias, float* __restrict__ Cout,
    int src_sel, int dst_sel)
{
    const int M = MROWS, N = D_MODEL, K = D_MODEL;
    (void)M;
    const float* A = gemm_src(src_sel, Ain);
    float* C = gemm_dst(dst_sel, Cout);

    __shared__ float As[16][132];   // A tile stored transposed [k][m], padded
    __shared__ float Bs[16][128];   // W tile [k][n]

    const int tid = threadIdx.x;
    const int tx = tid & 15;        // 0..15  -> N direction (8 cols each)
    const int ty = tid >> 4;        // 0..15  -> M direction (8 rows each)
    const int bx = blockIdx.x;      // N tile
    const int by = blockIdx.y;      // M tile

    const float* Ag = A + (size_t)by * 128 * K;
    const float* Wg = W + (size_t)bx * 128;

    const int a_row = tid >> 2;     // 0..63
    const int a_c4  = tid & 3;      // 0..3
    const int b_row = tid >> 5;     // 0..7
    const int b_c4  = tid & 31;     // 0..31

    float acc[8][8];
    #pragma unroll
    for (int i = 0; i < 8; i++)
        #pragma unroll
        for (int j = 0; j < 8; j++) acc[i][j] = 0.f;

    for (int k0 = 0; k0 < K; k0 += 16) {
        float4 av0 = *(const float4*)(Ag + (size_t)a_row        * K + k0 + a_c4 * 4);
        float4 av1 = *(const float4*)(Ag + (size_t)(a_row + 64) * K + k0 + a_c4 * 4);
        float4 bv0 = *(const float4*)(Wg + (size_t)(k0 + b_row)     * N + b_c4 * 4);
        float4 bv1 = *(const float4*)(Wg + (size_t)(k0 + b_row + 8) * N + b_c4 * 4);

        As[a_c4 * 4 + 0][a_row]      = av0.x;
        As[a_c4 * 4 + 1][a_row]      = av0.y;
        As[a_c4 * 4 + 2][a_row]      = av0.z;
        As[a_c4 * 4 + 3][a_row]      = av0.w;
        As[a_c4 * 4 + 0][a_row + 64] = av1.x;
        As[a_c4 * 4 + 1][a_row + 64] = av1.y;
        As[a_c4 * 4 + 2][a_row + 64] = av1.z;
        As[a_c4 * 4 + 3][a_row + 64] = av1.w;
        *(float4*)&Bs[b_row][b_c4 * 4]     = bv0;
        *(float4*)&Bs[b_row + 8][b_c4 * 4] = bv1;
        __syncthreads();

        #pragma unroll
        for (int k = 0; k < 16; k++) {
            float ra[8], rb[8];
            *(float4*)(ra)     = *(const float4*)&As[k][ty * 8];
            *(float4*)(ra + 4) = *(const float4*)&As[k][ty * 8 + 4];
            *(float4*)(rb)     = *(const float4*)&Bs[k][tx * 8];
            *(float4*)(rb + 4) = *(const float4*)&Bs[k][tx * 8 + 4];
            #pragma unroll
            for (int i = 0; i < 8; i++)
                #pragma unroll
                for (int j = 0; j < 8; j++)
                    acc[i][j] += ra[i] * rb[j];
        }
        __syncthreads();
    }

    // epilogue: add bias, write
    float bv[8];
    *(float4*)(bv)     = *(const float4*)(bias + bx * 128 + tx * 8);
    *(float4*)(bv + 4) = *(const float4*)(bias + bx * 128 + tx * 8 + 4);
    #pragma unroll
    for (int i = 0; i < 8; i++) {
        float* cp = C + (size_t)(by * 128 + ty * 8 + i) * N + bx * 128 + tx * 8;
        float4 o0, o1;
        o0.x = acc[i][0] + bv[0];  o0.y = acc[i][1] + bv[1];
        o0.z = acc[i][2] + bv[2];  o0.w = acc[i][3] + bv[3];
        o1.x = acc[i][4] + bv[4];  o1.y = acc[i][5] + bv[5];
        o1.z = acc[i][6] + bv[6];  o1.w = acc[i][7] + bv[7];
        *(float4*)(cp)     = o0;
        *(float4*)(cp + 4) = o1;
    }
}

// ============================================================================
// Flash attention (causal, fp32). Block = (q-tile of 64 rows, head, batch).
// 256 threads: thread t owns score row r = t>>2, interleaved key cols
// c = seg + 4*ci (seg = t&3, ci = 0..15) -> conflict-free K-tile reads with
// stride-68 smem rows. O accumulator: row r, contiguous dims d0=seg*16..+16.
// Reads g_Qp/g_Kp/g_Vp, writes g_At directly (device globals).
// ============================================================================
#define FA_STRIDE 68
#define FA_SMEM_BYTES (4 * 64 * FA_STRIDE * 4)

__global__ void __launch_bounds__(256) flash_attn_kernel(
    const float* __restrict__ mask)
{
    extern __shared__ float sm[];
    float* Qs = sm;
    float* Ks = sm + 64 * FA_STRIDE;
    float* Vs = sm + 2 * 64 * FA_STRIDE;
    float* Ps = sm + 3 * 64 * FA_STRIDE;

    const int qt  = blockIdx.x;   // 0..31
    const int h   = blockIdx.y;   // 0..15
    const int b   = blockIdx.z;   // 0..3
    const int tid = threadIdx.x;
    const int r   = tid >> 2;     // 0..63
    const int seg = tid & 3;      // 0..3
    const int d0  = seg * 16;

    const size_t base = ((size_t)b * S_LEN) * D_MODEL + h * HDIM;
    const float* mrow = mask + (size_t)b * S_LEN;

    // ---- load Q tile [64 x 64] ----
    {
        const int lr = tid >> 2;
        const int lc = (tid & 3) * 16;
        const float* src = g_Qp + base + (size_t)(qt * 64 + lr) * D_MODEL + lc;
        float* dst = Qs + lr * FA_STRIDE + lc;
        #pragma unroll
        for (int j = 0; j < 4; j++)
            *(float4*)(dst + 4 * j) = *(const float4*)(src + 4 * j);
    }

    float m_run = -1e30f, l_run = 0.f;
    float Oacc[16];
    #pragma unroll
    for (int i = 0; i < 16; i++) Oacc[i] = 0.f;

    const int qg = qt * 64 + r;
    const int ntiles = qt + 1;    // causal: only tiles with keys <= queries

    for (int kt = 0; kt < ntiles; kt++) {
        __syncthreads();          // protect K/V smem from previous iteration
        {
            const int lr = tid >> 2;
            const int lc = (tid & 3) * 16;
            const float* ksrc = g_Kp + base + (size_t)(kt * 64 + lr) * D_MODEL + lc;
            const float* vsrc = g_Vp + base + (size_t)(kt * 64 + lr) * D_MODEL + lc;
            float* kdst = Ks + lr * FA_STRIDE + lc;
            float* vdst = Vs + lr * FA_STRIDE + lc;
            #pragma unroll
            for (int j = 0; j < 4; j++) {
                *(float4*)(kdst + 4 * j) = *(const float4*)(ksrc + 4 * j);
                *(float4*)(vdst + 4 * j) = *(const float4*)(vsrc + 4 * j);
            }
        }
        __syncthreads();

        // ---- scores: s[ci] = Q[r,:] . K[seg+4ci,:] ----
        float s[16];
        #pragma unroll
        for (int i = 0; i < 16; i++) s[i] = 0.f;
        #pragma unroll 4
        for (int d = 0; d < 64; d += 4) {
            float4 q4 = *(const float4*)(Qs + r * FA_STRIDE + d);
            #pragma unroll
            for (int ci = 0; ci < 16; ci++) {
                float4 k4 = *(const float4*)(Ks + (seg + 4 * ci) * FA_STRIDE + d);
                s[ci] += q4.x * k4.x + q4.y * k4.y + q4.z * k4.z + q4.w * k4.w;
            }
        }

        // ---- scale + causal mask + additive padding mask ----
        float mx = -1e30f;
        #pragma unroll
        for (int ci = 0; ci < 16; ci++) {
            const int kg = kt * 64 + seg + 4 * ci;
            float sc = s[ci] * 0.125f + mrow[kg];   // 1/sqrt(64) = 0.125
            sc = (kg <= qg) ? sc : -1e30f;
            s[ci] = sc;
            mx = fmaxf(mx, sc);
        }
        // row reduce across the 4 threads of this row (adjacent lanes)
        mx = fmaxf(mx, __shfl_xor_sync(0xffffffffu, mx, 1));
        mx = fmaxf(mx, __shfl_xor_sync(0xffffffffu, mx, 2));
        const float m_new = fmaxf(m_run, mx);

        float lsum = 0.f;
        #pragma unroll
        for (int ci = 0; ci < 16; ci++) {
            float p = __expf(s[ci] - m_new);
            Ps[r * FA_STRIDE + seg + 4 * ci] = p;
            lsum += p;
        }
        lsum += __shfl_xor_sync(0xffffffffu, lsum, 1);
        lsum += __shfl_xor_sync(0xffffffffu, lsum, 2);

        const float alpha = __expf(m_run - m_new);
        l_run = l_run * alpha + lsum;
        m_run = m_new;
        #pragma unroll
        for (int i = 0; i < 16; i++) Oacc[i] *= alpha;

        __syncwarp();   // P row fully written by this row's 4 lanes (same warp)

        // ---- O += P @ V  (thread: row r, dims d0..d0+15) ----
        #pragma unroll 2
        for (int n = 0; n < 64; n++) {
            const float p = Ps[r * FA_STRIDE + n];
            const float* vrow = Vs + n * FA_STRIDE + d0;
            float4 v0 = *(const float4*)(vrow);
            float4 v1 = *(const float4*)(vrow + 4);
            float4 v2 = *(const float4*)(vrow + 8);
            float4 v3 = *(const float4*)(vrow + 12);
            Oacc[0]  += p * v0.x;  Oacc[1]  += p * v0.y;
            Oacc[2]  += p * v0.z;  Oacc[3]  += p * v0.w;
            Oacc[4]  += p * v1.x;  Oacc[5]  += p * v1.y;
            Oacc[6]  += p * v1.z;  Oacc[7]  += p * v1.w;
            Oacc[8]  += p * v2.x;  Oacc[9]  += p * v2.y;
            Oacc[10] += p * v2.z;  Oacc[11] += p * v2.w;
            Oacc[12] += p * v3.x;  Oacc[13] += p * v3.y;
            Oacc[14] += p * v3.z;  Oacc[15] += p * v3.w;
        }
    }

    // ---- normalize and write out (thread owns [qg, h*64 + d0 .. +16)) ----
    const float inv = 1.f / l_run;
    float* dst = g_At + base + (size_t)qg * D_MODEL + d0;
    float4 o;
    #pragma unroll
    for (int j = 0; j < 4; j++) {
        o.x = Oacc[4 * j + 0] * inv;
        o.y = Oacc[4 * j + 1] * inv;
        o.z = Oacc[4 * j + 2] * inv;
        o.w = Oacc[4 * j + 3] * inv;
        *(float4*)(dst + 4 * j) = o;
    }
}

// ============================================================================
// Launch
// ============================================================================
extern "C" void kernel_launch(void* const* d_in, const int* in_sizes, int n_in,
                              void* d_out, int out_size)
{
    const float* q    = (const float*)d_in[0];
    const float* k    = (const float*)d_in[1];
    const float* v    = (const float*)d_in[2];
    const float* mask = (const float*)d_in[3];
    const float* Wq   = (const float*)d_in[4];
    const float* bq   = (const float*)d_in[5];
    const float* Wk   = (const float*)d_in[6];
    const float* bk   = (const float*)d_in[7];
    const float* Wv   = (const float*)d_in[8];
    const float* bv   = (const float*)d_in[9];
    const float* Wp   = (const float*)d_in[10];
    const float* bp   = (const float*)d_in[11];
    float* out = (float*)d_out;

    static bool attr_set = false;
    if (!attr_set) {
        cudaFuncSetAttribute(flash_attn_kernel,
                             cudaFuncAttributeMaxDynamicSharedMemorySize,
                             FA_SMEM_BYTES);
        attr_set = true;
    }

    dim3 gemm_grid(D_MODEL / 128, MROWS / 128);   // (8, 64)
    // Q/K/V projections into device-global scratch (dst_sel 0/1/2)
    sgemm_bias_kernel<<<gemm_grid, 256>>>(q, Wq, bq, nullptr, 0, 0);
    sgemm_bias_kernel<<<gemm_grid, 256>>>(k, Wk, bk, nullptr, 0, 1);
    sgemm_bias_kernel<<<gemm_grid, 256>>>(v, Wv, bv, nullptr, 0, 2);

    dim3 fa_grid(S_LEN / 64, NHEAD, BATCH);       // (32, 16, 4)
    flash_attn_kernel<<<fa_grid, 256, FA_SMEM_BYTES>>>(mask);

    // output projection: src = g_At (src_sel 1), dst = d_out (dst_sel 3)
    sgemm_bias_kernel<<<gemm_grid, 256>>>(nullptr, Wp, bp, out, 1, 3);
}

// round 3
// speedup vs baseline: 1.4556x; 1.4556x over previous
#include <cuda_runtime.h>
#include <math.h>

// Problem constants
#define D_MODEL 1024
#define S_LEN   2048
#define BATCH   4
#define NHEAD   16
#define HDIM    64
#define MROWS   (BATCH * S_LEN)   // 8192

// -------------------- scratch (device globals; no allocation allowed) ------
__device__ float g_Qp[MROWS * D_MODEL];   // projected Q  [B,S,D]
__device__ float g_Kp[MROWS * D_MODEL];   // projected K
__device__ float g_Vp[MROWS * D_MODEL];   // projected V
__device__ float g_At[MROWS * D_MODEL];   // attention output (heads concat)

// dst selector: 0 -> g_Qp, 1 -> g_Kp, 2 -> g_Vp, 3 -> external (Cout)
__device__ __forceinline__ float* gemm_dst(int sel, float* Cout) {
    switch (sel) {
        case 0: return g_Qp;
        case 1: return g_Kp;
        case 2: return g_Vp;
        default: return Cout;
    }
}
// src selector: 0 -> external (Ain), 1 -> g_At
__device__ __forceinline__ const float* gemm_src(int sel, const float* Ain) {
    return (sel == 1) ? g_At : Ain;
}

// ============================================================================
// SGEMM: C[M,N] = A[M,K] @ W[K,N] + bias[N]     (M=8192, N=K=1024)
// 128x128 block tile, BK=16, 256 threads, 8x8 per-thread microtile.
// ============================================================================
__global__ void __launch_bounds__(256) sgemm_bias_kernel(
    const float* __restrict__ Ain, const float* __restrict__ W,
    const float* __restrict__ bias, float* __restrict__ Cout,
    int src_sel, int dst_sel)
{
    const int N = D_MODEL, K = D_MODEL;
    const float* A = gemm_src(src_sel, Ain);
    float* C = gemm_dst(dst_sel, Cout);

    __shared__ float As[16][132];   // A tile stored transposed [k][m], padded
    __shared__ float Bs[16][128];   // W tile [k][n]

    const int tid = threadIdx.x;
    const int tx = tid & 15;        // 0..15  -> N direction (8 cols each)
    const int ty = tid >> 4;        // 0..15  -> M direction (8 rows each)
    const int bx = blockIdx.x;      // N tile
    const int by = blockIdx.y;      // M tile

    const float* Ag = A + (size_t)by * 128 * K;
    const float* Wg = W + (size_t)bx * 128;

    const int a_row = tid >> 2;     // 0..63
    const int a_c4  = tid & 3;      // 0..3
    const int b_row = tid >> 5;     // 0..7
    const int b_c4  = tid & 31;     // 0..31

    float acc[8][8];
    #pragma unroll
    for (int i = 0; i < 8; i++)
        #pragma unroll
        for (int j = 0; j < 8; j++) acc[i][j] = 0.f;

    for (int k0 = 0; k0 < K; k0 += 16) {
        float4 av0 = *(const float4*)(Ag + (size_t)a_row        * K + k0 + a_c4 * 4);
        float4 av1 = *(const float4*)(Ag + (size_t)(a_row + 64) * K + k0 + a_c4 * 4);
        float4 bv0 = *(const float4*)(Wg + (size_t)(k0 + b_row)     * N + b_c4 * 4);
        float4 bv1 = *(const float4*)(Wg + (size_t)(k0 + b_row + 8) * N + b_c4 * 4);

        As[a_c4 * 4 + 0][a_row]      = av0.x;
        As[a_c4 * 4 + 1][a_row]      = av0.y;
        As[a_c4 * 4 + 2][a_row]      = av0.z;
        As[a_c4 * 4 + 3][a_row]      = av0.w;
        As[a_c4 * 4 + 0][a_row + 64] = av1.x;
        As[a_c4 * 4 + 1][a_row + 64] = av1.y;
        As[a_c4 * 4 + 2][a_row + 64] = av1.z;
        As[a_c4 * 4 + 3][a_row + 64] = av1.w;
        *(float4*)&Bs[b_row][b_c4 * 4]     = bv0;
        *(float4*)&Bs[b_row + 8][b_c4 * 4] = bv1;
        __syncthreads();

        #pragma unroll
        for (int k = 0; k < 16; k++) {
            float ra[8], rb[8];
            *(float4*)(ra)     = *(const float4*)&As[k][ty * 8];
            *(float4*)(ra + 4) = *(const float4*)&As[k][ty * 8 + 4];
            *(float4*)(rb)     = *(const float4*)&Bs[k][tx * 8];
            *(float4*)(rb + 4) = *(const float4*)&Bs[k][tx * 8 + 4];
            #pragma unroll
            for (int i = 0; i < 8; i++)
                #pragma unroll
                for (int j = 0; j < 8; j++)
                    acc[i][j] += ra[i] * rb[j];
        }
        __syncthreads();
    }

    // epilogue: add bias, write
    float bv[8];
    *(float4*)(bv)     = *(const float4*)(bias + bx * 128 + tx * 8);
    *(float4*)(bv + 4) = *(const float4*)(bias + bx * 128 + tx * 8 + 4);
    #pragma unroll
    for (int i = 0; i < 8; i++) {
        float* cp = C + (size_t)(by * 128 + ty * 8 + i) * N + bx * 128 + tx * 8;
        float4 o0, o1;
        o0.x = acc[i][0] + bv[0];  o0.y = acc[i][1] + bv[1];
        o0.z = acc[i][2] + bv[2];  o0.w = acc[i][3] + bv[3];
        o1.x = acc[i][4] + bv[4];  o1.y = acc[i][5] + bv[5];
        o1.z = acc[i][6] + bv[6];  o1.w = acc[i][7] + bv[7];
        *(float4*)(cp)     = o0;
        *(float4*)(cp + 4) = o1;
    }
}

// ============================================================================
// Flash attention (causal, fp32). Block = (q-tile of 64 rows, head, batch).
// 256 threads. Register-blocked 2 q-rows per thread:
//   thread t: rows r=t>>3 and r+32; key cols c = seg + 8*ci (seg=t&7, ci<8).
// QK: per 4-dim step, 2 Q-float4 + 8 K-float4 feed 128 FMA.
// PV: per 4 keys, 2 P-float4 + 8 V-float4 feed 256 FMA.
// K/V/Q smem stride 68 (conflict-free rows), P stride 72 (conflict-free
// 4x8 row/seg store pattern). Row reductions via shfl_xor 1,2,4 (8 lanes/row).
// ============================================================================
#define FA_STRIDE  68
#define FA_PSTRIDE 72
#define FA_SMEM_BYTES ((3 * 64 * FA_STRIDE + 64 * FA_PSTRIDE) * 4)

__global__ void __launch_bounds__(256) flash_attn_kernel(
    const float* __restrict__ mask)
{
    extern __shared__ float sm[];
    float* Qs = sm;
    float* Ks = Qs + 64 * FA_STRIDE;
    float* Vs = Ks + 64 * FA_STRIDE;
    float* Ps = Vs + 64 * FA_STRIDE;

    const int qt  = blockIdx.x;   // 0..31
    const int h   = blockIdx.y;   // 0..15
    const int b   = blockIdx.z;   // 0..3
    const int tid = threadIdx.x;
    const int r   = tid >> 3;     // 0..31
    const int seg = tid & 7;      // 0..7
    const int d0  = seg * 8;      // dim slice owned in PV / output

    const size_t base = ((size_t)b * S_LEN) * D_MODEL + h * HDIM;
    const float* mrow = mask + (size_t)b * S_LEN;

    // ---- load Q tile [64 x 64] ----
    {
        const int lr = tid >> 2;          // 0..63
        const int lc = (tid & 3) * 16;
        const float* src = g_Qp + base + (size_t)(qt * 64 + lr) * D_MODEL + lc;
        float* dst = Qs + lr * FA_STRIDE + lc;
        #pragma unroll
        for (int j = 0; j < 4; j++)
            *(float4*)(dst + 4 * j) = *(const float4*)(src + 4 * j);
    }

    float m_run[2] = {-1e30f, -1e30f};
    float l_run[2] = {0.f, 0.f};
    float Oacc[2][8];
    #pragma unroll
    for (int u = 0; u < 2; u++)
        #pragma unroll
        for (int j = 0; j < 8; j++) Oacc[u][j] = 0.f;

    const int qg0 = qt * 64 + r;          // row for u=0
    const int ntiles = qt + 1;            // causal: only tiles with keys <= queries

    for (int kt = 0; kt < ntiles; kt++) {
        __syncthreads();                  // protect K/V smem from previous iter
        {
            const int lr = tid >> 2;
            const int lc = (tid & 3) * 16;
            const float* ksrc = g_Kp + base + (size_t)(kt * 64 + lr) * D_MODEL + lc;
            const float* vsrc = g_Vp + base + (size_t)(kt * 64 + lr) * D_MODEL + lc;
            float* kdst = Ks + lr * FA_STRIDE + lc;
            float* vdst = Vs + lr * FA_STRIDE + lc;
            #pragma unroll
            for (int j = 0; j < 4; j++) {
                *(float4*)(kdst + 4 * j) = *(const float4*)(ksrc + 4 * j);
                *(float4*)(vdst + 4 * j) = *(const float4*)(vsrc + 4 * j);
            }
        }
        __syncthreads();

        // ---- scores: s[u][ci] = Q[r+32u,:] . K[seg+8ci,:] ----
        float s[2][8];
        #pragma unroll
        for (int u = 0; u < 2; u++)
            #pragma unroll
            for (int i = 0; i < 8; i++) s[u][i] = 0.f;

        #pragma unroll 4
        for (int d = 0; d < 64; d += 4) {
            float4 qa = *(const float4*)(Qs + r * FA_STRIDE + d);
            float4 qb = *(const float4*)(Qs + (r + 32) * FA_STRIDE + d);
            #pragma unroll
            for (int ci = 0; ci < 8; ci++) {
                float4 k4 = *(const float4*)(Ks + (seg + 8 * ci) * FA_STRIDE + d);
                s[0][ci] += qa.x * k4.x + qa.y * k4.y + qa.z * k4.z + qa.w * k4.w;
                s[1][ci] += qb.x * k4.x + qb.y * k4.y + qb.z * k4.z + qb.w * k4.w;
            }
        }

        // ---- per-row softmax update (2 rows per thread) ----
        #pragma unroll
        for (int u = 0; u < 2; u++) {
            const int qg = qg0 + 32 * u;
            float mx = -1e30f;
            #pragma unroll
            for (int ci = 0; ci < 8; ci++) {
                const int kg = kt * 64 + seg + 8 * ci;
                float sc = s[u][ci] * 0.125f + mrow[kg];   // 1/sqrt(64)
                sc = (kg <= qg) ? sc : -1e30f;
                s[u][ci] = sc;
                mx = fmaxf(mx, sc);
            }
            mx = fmaxf(mx, __shfl_xor_sync(0xffffffffu, mx, 1));
            mx = fmaxf(mx, __shfl_xor_sync(0xffffffffu, mx, 2));
            mx = fmaxf(mx, __shfl_xor_sync(0xffffffffu, mx, 4));
            const float m_new = fmaxf(m_run[u], mx);

            float lsum = 0.f;
            #pragma unroll
            for (int ci = 0; ci < 8; ci++) {
                float p = __expf(s[u][ci] - m_new);
                Ps[(r + 32 * u) * FA_PSTRIDE + seg + 8 * ci] = p;
                lsum += p;
            }
            lsum += __shfl_xor_sync(0xffffffffu, lsum, 1);
            lsum += __shfl_xor_sync(0xffffffffu, lsum, 2);
            lsum += __shfl_xor_sync(0xffffffffu, lsum, 4);

            const float alpha = __expf(m_run[u] - m_new);
            l_run[u] = l_run[u] * alpha + lsum;
            m_run[u] = m_new;
            #pragma unroll
            for (int j = 0; j < 8; j++) Oacc[u][j] *= alpha;
        }

        __syncwarp();   // P rows r, r+32 written entirely by this warp's lanes

        // ---- O += P @ V  (2 rows, dims d0..d0+7, 4 keys per step) ----
        #pragma unroll 2
        for (int n = 0; n < 64; n += 4) {
            float pa[4], pb[4];
            *(float4*)pa = *(const float4*)(Ps + r * FA_PSTRIDE + n);
            *(float4*)pb = *(const float4*)(Ps + (r + 32) * FA_PSTRIDE + n);
            #pragma unroll
            for (int j = 0; j < 4; j++) {
                const float* vrow = Vs + (n + j) * FA_STRIDE + d0;
                float4 v0 = *(const float4*)(vrow);
                float4 v1 = *(const float4*)(vrow + 4);
                const float p0 = pa[j], p1 = pb[j];
                Oacc[0][0] += p0 * v0.x;  Oacc[0][1] += p0 * v0.y;
                Oacc[0][2] += p0 * v0.z;  Oacc[0][3] += p0 * v0.w;
                Oacc[0][4] += p0 * v1.x;  Oacc[0][5] += p0 * v1.y;
                Oacc[0][6] += p0 * v1.z;  Oacc[0][7] += p0 * v1.w;
                Oacc[1][0] += p1 * v0.x;  Oacc[1][1] += p1 * v0.y;
                Oacc[1][2] += p1 * v0.z;  Oacc[1][3] += p1 * v0.w;
                Oacc[1][4] += p1 * v1.x;  Oacc[1][5] += p1 * v1.y;
                Oacc[1][6] += p1 * v1.z;  Oacc[1][7] += p1 * v1.w;
            }
        }
    }

    // ---- normalize and write out (rows qg0, qg0+32; dims d0..d0+7) ----
    #pragma unroll
    for (int u = 0; u < 2; u++) {
        const float inv = 1.f / l_run[u];
        float* dst = g_At + base + (size_t)(qg0 + 32 * u) * D_MODEL + d0;
        float4 o0, o1;
        o0.x = Oacc[u][0] * inv;  o0.y = Oacc[u][1] * inv;
        o0.z = Oacc[u][2] * inv;  o0.w = Oacc[u][3] * inv;
        o1.x = Oacc[u][4] * inv;  o1.y = Oacc[u][5] * inv;
        o1.z = Oacc[u][6] * inv;  o1.w = Oacc[u][7] * inv;
        *(float4*)(dst)     = o0;
        *(float4*)(dst + 4) = o1;
    }
}

// ============================================================================
// Launch
// ============================================================================
extern "C" void kernel_launch(void* const* d_in, const int* in_sizes, int n_in,
                              void* d_out, int out_size)
{
    const float* q    = (const float*)d_in[0];
    const float* k    = (const float*)d_in[1];
    const float* v    = (const float*)d_in[2];
    const float* mask = (const float*)d_in[3];
    const float* Wq   = (const float*)d_in[4];
    const float* bq   = (const float*)d_in[5];
    const float* Wk   = (const float*)d_in[6];
    const float* bk   = (const float*)d_in[7];
    const float* Wv   = (const float*)d_in[8];
    const float* bv   = (const float*)d_in[9];
    const float* Wp   = (const float*)d_in[10];
    const float* bp   = (const float*)d_in[11];
    float* out = (float*)d_out;

    cudaFuncSetAttribute(flash_attn_kernel,
                         cudaFuncAttributeMaxDynamicSharedMemorySize,
                         FA_SMEM_BYTES);

    dim3 gemm_grid(D_MODEL / 128, MROWS / 128);   // (8, 64)
    // Q/K/V projections into device-global scratch (dst_sel 0/1/2)
    sgemm_bias_kernel<<<gemm_grid, 256>>>(q, Wq, bq, nullptr, 0, 0);
    sgemm_bias_kernel<<<gemm_grid, 256>>>(k, Wk, bk, nullptr, 0, 1);
    sgemm_bias_kernel<<<gemm_grid, 256>>>(v, Wv, bv, nullptr, 0, 2);

    dim3 fa_grid(S_LEN / 64, NHEAD, BATCH);       // (32, 16, 4)
    flash_attn_kernel<<<fa_grid, 256, FA_SMEM_BYTES>>>(mask);

    // output projection: src = g_At (src_sel 1), dst = d_out (dst_sel 3)
    sgemm_bias_kernel<<<gemm_grid, 256>>>(nullptr, Wp, bp, out, 1, 3);
}

// round 4
// speedup vs baseline: 1.8890x; 1.2978x over previous
#include <cuda_runtime.h>
#include <math.h>

// Problem constants
#define D_MODEL 1024
#define S_LEN   2048
#define BATCH   4
#define NHEAD   16
#define HDIM    64
#define MROWS   (BATCH * S_LEN)   // 8192

// -------------------- scratch (device globals; no allocation allowed) ------
__device__ float g_Qp[MROWS * D_MODEL];   // projected Q  [B,S,D]
__device__ float g_Kp[MROWS * D_MODEL];   // projected K
__device__ float g_Vp[MROWS * D_MODEL];   // projected V
__device__ float g_At[MROWS * D_MODEL];   // attention output (heads concat)

// dst selector: 0 -> g_Qp, 1 -> g_Kp, 2 -> g_Vp, 3 -> external (Cout)
__device__ __forceinline__ float* gemm_dst(int sel, float* Cout) {
    switch (sel) {
        case 0: return g_Qp;
        case 1: return g_Kp;
        case 2: return g_Vp;
        default: return Cout;
    }
}
// src selector: 0 -> external (Ain), 1 -> g_At
__device__ __forceinline__ const float* gemm_src(int sel, const float* Ain) {
    return (sel == 1) ? g_At : Ain;
}

// ============================================================================
// SGEMM: C[M,N] = A[M,K] @ W[K,N] + bias[N]     (M=8192, N=K=1024)
// 128x128 block tile, BK=16, 256 threads, 8x8 per-thread microtile.
// (~90% of FFMA roofline; tensor-core replacement is the next lever.)
// ============================================================================
__global__ void __launch_bounds__(256) sgemm_bias_kernel(
    const float* __restrict__ Ain, const float* __restrict__ W,
    const float* __restrict__ bias, float* __restrict__ Cout,
    int src_sel, int dst_sel)
{
    const int N = D_MODEL, K = D_MODEL;
    const float* A = gemm_src(src_sel, Ain);
    float* C = gemm_dst(dst_sel, Cout);

    __shared__ float As[16][132];   // A tile stored transposed [k][m], padded
    __shared__ float Bs[16][128];   // W tile [k][n]

    const int tid = threadIdx.x;
    const int tx = tid & 15;
    const int ty = tid >> 4;
    const int bx = blockIdx.x;
    const int by = blockIdx.y;

    const float* Ag = A + (size_t)by * 128 * K;
    const float* Wg = W + (size_t)bx * 128;

    const int a_row = tid >> 2;
    const int a_c4  = tid & 3;
    const int b_row = tid >> 5;
    const int b_c4  = tid & 31;

    float acc[8][8];
    #pragma unroll
    for (int i = 0; i < 8; i++)
        #pragma unroll
        for (int j = 0; j < 8; j++) acc[i][j] = 0.f;

    for (int k0 = 0; k0 < K; k0 += 16) {
        float4 av0 = *(const float4*)(Ag + (size_t)a_row        * K + k0 + a_c4 * 4);
        float4 av1 = *(const float4*)(Ag + (size_t)(a_row + 64) * K + k0 + a_c4 * 4);
        float4 bv0 = *(const float4*)(Wg + (size_t)(k0 + b_row)     * N + b_c4 * 4);
        float4 bv1 = *(const float4*)(Wg + (size_t)(k0 + b_row + 8) * N + b_c4 * 4);

        As[a_c4 * 4 + 0][a_row]      = av0.x;
        As[a_c4 * 4 + 1][a_row]      = av0.y;
        As[a_c4 * 4 + 2][a_row]      = av0.z;
        As[a_c4 * 4 + 3][a_row]      = av0.w;
        As[a_c4 * 4 + 0][a_row + 64] = av1.x;
        As[a_c4 * 4 + 1][a_row + 64] = av1.y;
        As[a_c4 * 4 + 2][a_row + 64] = av1.z;
        As[a_c4 * 4 + 3][a_row + 64] = av1.w;
        *(float4*)&Bs[b_row][b_c4 * 4]     = bv0;
        *(float4*)&Bs[b_row + 8][b_c4 * 4] = bv1;
        __syncthreads();

        #pragma unroll
        for (int k = 0; k < 16; k++) {
            float ra[8], rb[8];
            *(float4*)(ra)     = *(const float4*)&As[k][ty * 8];
            *(float4*)(ra + 4) = *(const float4*)&As[k][ty * 8 + 4];
            *(float4*)(rb)     = *(const float4*)&Bs[k][tx * 8];
            *(float4*)(rb + 4) = *(const float4*)&Bs[k][tx * 8 + 4];
            #pragma unroll
            for (int i = 0; i < 8; i++)
                #pragma unroll
                for (int j = 0; j < 8; j++)
                    acc[i][j] += ra[i] * rb[j];
        }
        __syncthreads();
    }

    float bv[8];
    *(float4*)(bv)     = *(const float4*)(bias + bx * 128 + tx * 8);
    *(float4*)(bv + 4) = *(const float4*)(bias + bx * 128 + tx * 8 + 4);
    #pragma unroll
    for (int i = 0; i < 8; i++) {
        float* cp = C + (size_t)(by * 128 + ty * 8 + i) * N + bx * 128 + tx * 8;
        float4 o0, o1;
        o0.x = acc[i][0] + bv[0];  o0.y = acc[i][1] + bv[1];
        o0.z = acc[i][2] + bv[2];  o0.w = acc[i][3] + bv[3];
        o1.x = acc[i][4] + bv[4];  o1.y = acc[i][5] + bv[5];
        o1.z = acc[i][6] + bv[6];  o1.w = acc[i][7] + bv[7];
        *(float4*)(cp)     = o0;
        *(float4*)(cp + 4) = o1;
    }
}

// ============================================================================
// Flash attention (causal, fp32). Block = (q-tile of 128 rows, head, batch).
// 256 threads, 4 q-rows per thread: rows r+32u (r=tid>>3, u=0..3),
// key cols c = seg + 8*ci (seg=tid&7, ci<8).
// QK per 4-dim step: 4 Q + 8 K float4 -> 128 FMA.  PV per 4-key step:
// 4 P + 8 V float4 -> 128 FMA.  FFMA-bound (LDS cyc < FFMA cyc).
// V loads phase-swizzled (segs>=4 load upper float4 first) -> all 32 banks
// distinct per instruction. Heavy q-tiles launched first (causal balance).
// ============================================================================
#define FA_STRIDE  68
#define FA_PSTRIDE 72
#define FA_QROWS   128
#define FA_SMEM_BYTES ((FA_QROWS * FA_STRIDE + 2 * 64 * FA_STRIDE + FA_QROWS * FA_PSTRIDE) * 4)

__global__ void __launch_bounds__(256) flash_attn_kernel(
    const float* __restrict__ mask)
{
    extern __shared__ float sm[];
    float* Qs = sm;                               // [128][68]
    float* Ks = Qs + FA_QROWS * FA_STRIDE;        // [64][68]
    float* Vs = Ks + 64 * FA_STRIDE;              // [64][68]
    float* Ps = Vs + 64 * FA_STRIDE;              // [128][72]

    const int qt  = (int)gridDim.x - 1 - (int)blockIdx.x;  // heavy tiles first
    const int h   = blockIdx.y;
    const int b   = blockIdx.z;
    const int tid = threadIdx.x;
    const int r   = tid >> 3;     // 0..31
    const int seg = tid & 7;      // 0..7
    const int d0  = seg * 8;      // dim slice owned in PV / output
    const int offx = seg & 4;     // phase swizzle: 0 for segs 0-3, 4 for 4-7
    const int offy = 4 - offx;

    const size_t base = ((size_t)b * S_LEN) * D_MODEL + h * HDIM;
    const float* mrow = mask + (size_t)b * S_LEN;

    // ---- load Q tile [128 x 64] ----
    {
        const int lr = tid >> 1;          // 0..127
        const int lc = (tid & 1) * 32;
        const float* src = g_Qp + base + (size_t)(qt * FA_QROWS + lr) * D_MODEL + lc;
        float* dst = Qs + lr * FA_STRIDE + lc;
        #pragma unroll
        for (int j = 0; j < 8; j++)
            *(float4*)(dst + 4 * j) = *(const float4*)(src + 4 * j);
    }

    float m_run[4] = {-1e30f, -1e30f, -1e30f, -1e30f};
    float l_run[4] = {0.f, 0.f, 0.f, 0.f};
    float Oacc[4][8];
    #pragma unroll
    for (int u = 0; u < 4; u++)
        #pragma unroll
        for (int j = 0; j < 8; j++) Oacc[u][j] = 0.f;

    const int qg0 = qt * FA_QROWS + r;    // row for u=0; rows are qg0 + 32u
    const int ntiles = 2 * qt + 2;        // causal: keys <= last query of tile

    for (int kt = 0; kt < ntiles; kt++) {
        __syncthreads();                  // protect K/V smem from previous iter
        {
            const int lr = tid >> 2;      // 0..63
            const int lc = (tid & 3) * 16;
            const float* ksrc = g_Kp + base + (size_t)(kt * 64 + lr) * D_MODEL + lc;
            const float* vsrc = g_Vp + base + (size_t)(kt * 64 + lr) * D_MODEL + lc;
            float* kdst = Ks + lr * FA_STRIDE + lc;
            float* vdst = Vs + lr * FA_STRIDE + lc;
            #pragma unroll
            for (int j = 0; j < 4; j++) {
                *(float4*)(kdst + 4 * j) = *(const float4*)(ksrc + 4 * j);
                *(float4*)(vdst + 4 * j) = *(const float4*)(vsrc + 4 * j);
            }
        }
        __syncthreads();

        // ---- scores: s[u][ci] = Q[r+32u,:] . K[seg+8ci,:] ----
        float s[4][8];
        #pragma unroll
        for (int u = 0; u < 4; u++)
            #pragma unroll
            for (int i = 0; i < 8; i++) s[u][i] = 0.f;

        #pragma unroll 4
        for (int d = 0; d < 64; d += 4) {
            float4 q0 = *(const float4*)(Qs + r * FA_STRIDE + d);
            float4 q1 = *(const float4*)(Qs + (r + 32) * FA_STRIDE + d);
            float4 q2 = *(const float4*)(Qs + (r + 64) * FA_STRIDE + d);
            float4 q3 = *(const float4*)(Qs + (r + 96) * FA_STRIDE + d);
            #pragma unroll
            for (int ci = 0; ci < 8; ci++) {
                float4 k4 = *(const float4*)(Ks + (seg + 8 * ci) * FA_STRIDE + d);
                s[0][ci] += q0.x * k4.x + q0.y * k4.y + q0.z * k4.z + q0.w * k4.w;
                s[1][ci] += q1.x * k4.x + q1.y * k4.y + q1.z * k4.z + q1.w * k4.w;
                s[2][ci] += q2.x * k4.x + q2.y * k4.y + q2.z * k4.z + q2.w * k4.w;
                s[3][ci] += q3.x * k4.x + q3.y * k4.y + q3.z * k4.z + q3.w * k4.w;
            }
        }

        // mask values depend only on key index -> load once, reuse for all u
        float mvv[8];
        #pragma unroll
        for (int ci = 0; ci < 8; ci++)
            mvv[ci] = mrow[kt * 64 + seg + 8 * ci];

        // ---- per-row softmax update (4 rows per thread) ----
        #pragma unroll
        for (int u = 0; u < 4; u++) {
            const int qg = qg0 + 32 * u;
            float mx = -1e30f;
            #pragma unroll
            for (int ci = 0; ci < 8; ci++) {
                const int kg = kt * 64 + seg + 8 * ci;
                float sc = s[u][ci] * 0.125f + mvv[ci];   // 1/sqrt(64)
                sc = (kg <= qg) ? sc : -1e30f;
                s[u][ci] = sc;
                mx = fmaxf(mx, sc);
            }
            mx = fmaxf(mx, __shfl_xor_sync(0xffffffffu, mx, 1));
            mx = fmaxf(mx, __shfl_xor_sync(0xffffffffu, mx, 2));
            mx = fmaxf(mx, __shfl_xor_sync(0xffffffffu, mx, 4));
            const float m_new = fmaxf(m_run[u], mx);

            float lsum = 0.f;
            #pragma unroll
            for (int ci = 0; ci < 8; ci++) {
                float p = __expf(s[u][ci] - m_new);
                Ps[(r + 32 * u) * FA_PSTRIDE + seg + 8 * ci] = p;
                lsum += p;
            }
            lsum += __shfl_xor_sync(0xffffffffu, lsum, 1);
            lsum += __shfl_xor_sync(0xffffffffu, lsum, 2);
            lsum += __shfl_xor_sync(0xffffffffu, lsum, 4);

            const float alpha = __expf(m_run[u] - m_new);
            l_run[u] = l_run[u] * alpha + lsum;
            m_run[u] = m_new;
            #pragma unroll
            for (int j = 0; j < 8; j++) Oacc[u][j] *= alpha;
        }

        __syncwarp();   // P rows r+32u written entirely by this warp's lanes

        // ---- O += P @ V  (4 rows, dims d0..d0+7 phase-swizzled, 4 keys/step)
        // Oacc slots 0-3 accumulate the float4 at d0+offx, slots 4-7 at d0+offy.
        #pragma unroll 2
        for (int n = 0; n < 64; n += 4) {
            float p0[4], p1[4], p2[4], p3[4];
            *(float4*)p0 = *(const float4*)(Ps + r * FA_PSTRIDE + n);
            *(float4*)p1 = *(const float4*)(Ps + (r + 32) * FA_PSTRIDE + n);
            *(float4*)p2 = *(const float4*)(Ps + (r + 64) * FA_PSTRIDE + n);
            *(float4*)p3 = *(const float4*)(Ps + (r + 96) * FA_PSTRIDE + n);
            #pragma unroll
            for (int j = 0; j < 4; j++) {
                const float* vrow = Vs + (n + j) * FA_STRIDE + d0;
                float4 vx = *(const float4*)(vrow + offx);
                float4 vy = *(const float4*)(vrow + offy);
                const float a0 = p0[j], a1 = p1[j], a2 = p2[j], a3 = p3[j];
                Oacc[0][0] += a0 * vx.x;  Oacc[0][1] += a0 * vx.y;
                Oacc[0][2] += a0 * vx.z;  Oacc[0][3] += a0 * vx.w;
                Oacc[0][4] += a0 * vy.x;  Oacc[0][5] += a0 * vy.y;
                Oacc[0][6] += a0 * vy.z;  Oacc[0][7] += a0 * vy.w;
                Oacc[1][0] += a1 * vx.x;  Oacc[1][1] += a1 * vx.y;
                Oacc[1][2] += a1 * vx.z;  Oacc[1][3] += a1 * vx.w;
                Oacc[1][4] += a1 * vy.x;  Oacc[1][5] += a1 * vy.y;
                Oacc[1][6] += a1 * vy.z;  Oacc[1][7] += a1 * vy.w;
                Oacc[2][0] += a2 * vx.x;  Oacc[2][1] += a2 * vx.y;
                Oacc[2][2] += a2 * vx.z;  Oacc[2][3] += a2 * vx.w;
                Oacc[2][4] += a2 * vy.x;  Oacc[2][5] += a2 * vy.y;
                Oacc[2][6] += a2 * vy.z;  Oacc[2][7] += a2 * vy.w;
                Oacc[3][0] += a3 * vx.x;  Oacc[3][1] += a3 * vx.y;
                Oacc[3][2] += a3 * vx.z;  Oacc[3][3] += a3 * vx.w;
                Oacc[3][4] += a3 * vy.x;  Oacc[3][5] += a3 * vy.y;
                Oacc[3][6] += a3 * vy.z;  Oacc[3][7] += a3 * vy.w;
            }
        }
    }

    // ---- normalize and write out (rows qg0+32u; slots 0-3 -> d0+offx, 4-7 -> d0+offy)
    #pragma unroll
    for (int u = 0; u < 4; u++) {
        const float inv = 1.f / l_run[u];
        float* dst = g_At + base + (size_t)(qg0 + 32 * u) * D_MODEL + d0;
        float4 ox, oy;
        ox.x = Oacc[u][0] * inv;  ox.y = Oacc[u][1] * inv;
        ox.z = Oacc[u][2] * inv;  ox.w = Oacc[u][3] * inv;
        oy.x = Oacc[u][4] * inv;  oy.y = Oacc[u][5] * inv;
        oy.z = Oacc[u][6] * inv;  oy.w = Oacc[u][7] * inv;
        *(float4*)(dst + offx) = ox;
        *(float4*)(dst + offy) = oy;
    }
}

// ============================================================================
// Launch
// ============================================================================
extern "C" void kernel_launch(void* const* d_in, const int* in_sizes, int n_in,
                              void* d_out, int out_size)
{
    const float* q    = (const float*)d_in[0];
    const float* k    = (const float*)d_in[1];
    const float* v    = (const float*)d_in[2];
    const float* mask = (const float*)d_in[3];
    const float* Wq   = (const float*)d_in[4];
    const float* bq   = (const float*)d_in[5];
    const float* Wk   = (const float*)d_in[6];
    const float* bk   = (const float*)d_in[7];
    const float* Wv   = (const float*)d_in[8];
    const float* bv   = (const float*)d_in[9];
    const float* Wp   = (const float*)d_in[10];
    const float* bp   = (const float*)d_in[11];
    float* out = (float*)d_out;

    cudaFuncSetAttribute(flash_attn_kernel,
                         cudaFuncAttributeMaxDynamicSharedMemorySize,
                         FA_SMEM_BYTES);

    dim3 gemm_grid(D_MODEL / 128, MROWS / 128);   // (8, 64)
    sgemm_bias_kernel<<<gemm_grid, 256>>>(q, Wq, bq, nullptr, 0, 0);
    sgemm_bias_kernel<<<gemm_grid, 256>>>(k, Wk, bk, nullptr, 0, 1);
    sgemm_bias_kernel<<<gemm_grid, 256>>>(v, Wv, bv, nullptr, 0, 2);

    dim3 fa_grid(S_LEN / FA_QROWS, NHEAD, BATCH); // (16, 16, 4)
    flash_attn_kernel<<<fa_grid, 256, FA_SMEM_BYTES>>>(mask);

    sgemm_bias_kernel<<<gemm_grid, 256>>>(nullptr, Wp, bp, out, 1, 3);
}

// round 8
// speedup vs baseline: 4.4950x; 2.3796x over previous
#include <cuda_runtime.h>
#include <cstdint>
#include <math.h>

// Problem constants
#define D_MODEL 1024
#define S_LEN   2048
#define BATCH   4
#define NHEAD   16
#define HDIM    64
#define MROWS   (BATCH * S_LEN)   // 8192

// -------------------- scratch (device globals; no allocation allowed) ------
__device__ float g_Qp[MROWS * D_MODEL];
__device__ float g_Kp[MROWS * D_MODEL];
__device__ float g_Vp[MROWS * D_MODEL];
__device__ float g_At[MROWS * D_MODEL];

__device__ __forceinline__ float* gemm_dst(int sel, float* Cout) {
    switch (sel) {
        case 0: return g_Qp;
        case 1: return g_Kp;
        case 2: return g_Vp;
        default: return Cout;
    }
}
__device__ __forceinline__ const float* gemm_src(int sel, const float* Ain) {
    return (sel == 1) ? g_At : Ain;
}

__device__ __forceinline__ float f32_to_tf32(float x) {
    uint32_t u;
    asm("cvt.rna.tf32.f32 %0, %1;" : "=r"(u) : "f"(x));
    return __uint_as_float(u);
}
__device__ __forceinline__ void mma16888(float& d0, float& d1, float& d2, float& d3,
                                         uint32_t a0, uint32_t a1, uint32_t a2, uint32_t a3,
                                         uint32_t b0, uint32_t b1) {
    asm volatile(
        "mma.sync.aligned.m16n8k8.row.col.f32.tf32.tf32.f32 "
        "{%0,%1,%2,%3}, {%4,%5,%6,%7}, {%8,%9}, {%0,%1,%2,%3};"
        : "+f"(d0), "+f"(d1), "+f"(d2), "+f"(d3)
        : "r"(a0), "r"(a1), "r"(a2), "r"(a3), "r"(b0), "r"(b1));
}

// ============================================================================
// tf32 tensor-core GEMM via mma.sync (m16n8k8):  [unchanged from round 7]
// ============================================================================
#define GA_STRIDE 36
#define GB_STRIDE 132

__global__ void __launch_bounds__(256, 2) mma_gemm_kernel(
    const float* __restrict__ Ain, const float* __restrict__ W,
    const float* __restrict__ bias, float* __restrict__ Cout,
    int src_sel, int dst_sel)
{
    const int N = D_MODEL, K = D_MODEL;
    const float* A = gemm_src(src_sel, Ain);
    float* C = gemm_dst(dst_sel, Cout);

    __shared__ float As[128 * GA_STRIDE];
    __shared__ float Bs[32 * GB_STRIDE];

    const int tid  = threadIdx.x;
    const int wid  = tid >> 5;
    const int lane = tid & 31;
    const int grp  = lane >> 2;
    const int tig  = lane & 3;
    const int wm   = (wid >> 2) * 64;
    const int wn   = (wid & 3) * 32;
    const int bx = blockIdx.x, by = blockIdx.y;

    const float* Ag = A + (size_t)by * 128 * K;
    const int arow = tid >> 3;
    const int ac4  = (tid & 7) * 4;
    const int brow = tid >> 5;
    const int bc4  = (tid & 31) * 4;

    float acc[4][4][4];
    #pragma unroll
    for (int mt = 0; mt < 4; mt++)
        #pragma unroll
        for (int nt = 0; nt < 4; nt++)
            #pragma unroll
            for (int c = 0; c < 4; c++) acc[mt][nt][c] = 0.f;

    const uint32_t* Asu = (const uint32_t*)As;
    const uint32_t* Bsu = (const uint32_t*)Bs;

    for (int ch = 0; ch < 32; ch++) {
        const int k0 = ch * 32;
        float4 av[4], bv[4];
        #pragma unroll
        for (int i = 0; i < 4; i++) {
            av[i] = *(const float4*)(Ag + (size_t)(arow + i * 32) * K + k0 + ac4);
            av[i].x = f32_to_tf32(av[i].x);  av[i].y = f32_to_tf32(av[i].y);
            av[i].z = f32_to_tf32(av[i].z);  av[i].w = f32_to_tf32(av[i].w);
            bv[i] = *(const float4*)(W + (size_t)(k0 + brow + i * 8) * N + bx * 128 + bc4);
            bv[i].x = f32_to_tf32(bv[i].x);  bv[i].y = f32_to_tf32(bv[i].y);
            bv[i].z = f32_to_tf32(bv[i].z);  bv[i].w = f32_to_tf32(bv[i].w);
        }
        __syncthreads();
        #pragma unroll
        for (int i = 0; i < 4; i++) {
            *(float4*)(As + (arow + i * 32) * GA_STRIDE + ac4) = av[i];
            *(float4*)(Bs + (brow + i * 8) * GB_STRIDE + bc4)  = bv[i];
        }
        __syncthreads();

        #pragma unroll
        for (int ks = 0; ks < 4; ks++) {
            uint32_t afr[4][4];
            #pragma unroll
            for (int mt = 0; mt < 4; mt++) {
                const int base = (wm + mt * 16 + grp) * GA_STRIDE + ks * 8 + tig;
                afr[mt][0] = Asu[base];
                afr[mt][1] = Asu[base + 8 * GA_STRIDE];
                afr[mt][2] = Asu[base + 4];
                afr[mt][3] = Asu[base + 8 * GA_STRIDE + 4];
            }
            uint32_t bfr[4][2];
            #pragma unroll
            for (int nt = 0; nt < 4; nt++) {
                const int bb = (ks * 8 + tig) * GB_STRIDE + wn + nt * 8 + grp;
                bfr[nt][0] = Bsu[bb];
                bfr[nt][1] = Bsu[bb + 4 * GB_STRIDE];
            }
            #pragma unroll
            for (int mt = 0; mt < 4; mt++)
                #pragma unroll
                for (int nt = 0; nt < 4; nt++)
                    mma16888(acc[mt][nt][0], acc[mt][nt][1],
                             acc[mt][nt][2], acc[mt][nt][3],
                             afr[mt][0], afr[mt][1], afr[mt][2], afr[mt][3],
                             bfr[nt][0], bfr[nt][1]);
        }
    }

    float2 bias2[4];
    #pragma unroll
    for (int nt = 0; nt < 4; nt++)
        bias2[nt] = *(const float2*)(bias + bx * 128 + wn + nt * 8 + tig * 2);

    #pragma unroll
    for (int mt = 0; mt < 4; mt++) {
        const int row = by * 128 + wm + mt * 16 + grp;
        #pragma unroll
        for (int nt = 0; nt < 4; nt++) {
            const int col = bx * 128 + wn + nt * 8 + tig * 2;
            float2 v0, v1;
            v0.x = acc[mt][nt][0] + bias2[nt].x;
            v0.y = acc[mt][nt][1] + bias2[nt].y;
            v1.x = acc[mt][nt][2] + bias2[nt].x;
            v1.y = acc[mt][nt][3] + bias2[nt].y;
            *(float2*)(C + (size_t)row * N + col)       = v0;
            *(float2*)(C + (size_t)(row + 8) * N + col) = v1;
        }
    }
}

// ============================================================================
// Flash attention with mma.sync tf32 (causal). Block = (128 q-rows, head, b).
// 8 warps; warp w owns q-rows [16w, 16w+16). Q fragments held in registers
// for the whole block. K/V tiles 64x64 in smem (stride 68, tf32-rounded).
// QK: 8x8 m16n8k8; softmax in C-layout (row = 4 lanes -> shfl_xor 1,2);
// P -> per-warp-private smem (syncwarp only) -> A frags for PV: 8x8 mma.
// All fragment LDS conflict-free (banks 4*grp+tig / 4*tig+grp).
// ============================================================================
#define FA2_STR 68
#define FA2_SMEM_BYTES ((64 * FA2_STR + 64 * FA2_STR + 128 * FA2_STR) * 4)

__global__ void __launch_bounds__(256) flash_attn_mma_kernel(
    const float* __restrict__ mask)
{
    extern __shared__ float sm[];
    float* Ks = sm;                       // [64][68]
    float* Vs = Ks + 64 * FA2_STR;        // [64][68]
    float* Ps = Vs + 64 * FA2_STR;        // [128][68]
    const uint32_t* Ksu = (const uint32_t*)Ks;
    const uint32_t* Vsu = (const uint32_t*)Vs;
    const uint32_t* Psu = (const uint32_t*)Ps;

    const int qt  = (int)gridDim.x - 1 - (int)blockIdx.x;  // heavy tiles first
    const int h   = blockIdx.y;
    const int b   = blockIdx.z;
    const int tid = threadIdx.x;
    const int wid = tid >> 5, lane = tid & 31;
    const int grp = lane >> 2, tig = lane & 3;
    const int wrow = wid * 16;

    const size_t base = ((size_t)b * S_LEN) * D_MODEL + h * HDIM;
    const float* mrow = mask + (size_t)b * S_LEN;

    // ---- Q fragments in registers (reused for every k-tile) ----
    uint32_t qa[8][4];
    {
        const float* Qg = g_Qp + base + (size_t)(qt * 128 + wrow) * D_MODEL;
        #pragma unroll
        for (int ks = 0; ks < 8; ks++) {
            qa[ks][0] = __float_as_uint(f32_to_tf32(Qg[(size_t)grp       * D_MODEL + ks * 8 + tig]));
            qa[ks][1] = __float_as_uint(f32_to_tf32(Qg[(size_t)(grp + 8) * D_MODEL + ks * 8 + tig]));
            qa[ks][2] = __float_as_uint(f32_to_tf32(Qg[(size_t)grp       * D_MODEL + ks * 8 + tig + 4]));
            qa[ks][3] = __float_as_uint(f32_to_tf32(Qg[(size_t)(grp + 8) * D_MODEL + ks * 8 + tig + 4]));
        }
    }

    float Oacc[8][4];
    #pragma unroll
    for (int nt = 0; nt < 8; nt++)
        #pragma unroll
        for (int c = 0; c < 4; c++) Oacc[nt][c] = 0.f;
    float m_run[2] = {-1e30f, -1e30f};
    float l_run[2] = {0.f, 0.f};

    const int qg0 = qt * 128 + wrow + grp;   // row for u=0 (u=1: +8)
    const int ntiles = 2 * qt + 2;

    for (int kt = 0; kt < ntiles; kt++) {
        __syncthreads();     // all warps done with previous K/V tiles
        {
            const int lr = tid >> 2;            // 0..63
            const int lc = (tid & 3) * 16;
            const float* ksrc = g_Kp + base + (size_t)(kt * 64 + lr) * D_MODEL + lc;
            const float* vsrc = g_Vp + base + (size_t)(kt * 64 + lr) * D_MODEL + lc;
            float* kdst = Ks + lr * FA2_STR + lc;
            float* vdst = Vs + lr * FA2_STR + lc;
            #pragma unroll
            for (int j = 0; j < 4; j++) {
                float4 kv = *(const float4*)(ksrc + 4 * j);
                kv.x = f32_to_tf32(kv.x);  kv.y = f32_to_tf32(kv.y);
                kv.z = f32_to_tf32(kv.z);  kv.w = f32_to_tf32(kv.w);
                *(float4*)(kdst + 4 * j) = kv;
                float4 vv = *(const float4*)(vsrc + 4 * j);
                vv.x = f32_to_tf32(vv.x);  vv.y = f32_to_tf32(vv.y);
                vv.z = f32_to_tf32(vv.z);  vv.w = f32_to_tf32(vv.w);
                *(float4*)(vdst + 4 * j) = vv;
            }
        }
        __syncthreads();

        // ---- scores S = Q @ K^T  (16 rows x 64 keys per warp) ----
        float sacc[8][4];
        #pragma unroll
        for (int nt = 0; nt < 8; nt++)
            #pragma unroll
            for (int c = 0; c < 4; c++) sacc[nt][c] = 0.f;

        #pragma unroll
        for (int ks = 0; ks < 8; ks++) {
            #pragma unroll
            for (int nt = 0; nt < 8; nt++) {
                const int bb = (nt * 8 + grp) * FA2_STR + ks * 8 + tig;
                uint32_t b0 = Ksu[bb];
                uint32_t b1 = Ksu[bb + 4];
                mma16888(sacc[nt][0], sacc[nt][1], sacc[nt][2], sacc[nt][3],
                         qa[ks][0], qa[ks][1], qa[ks][2], qa[ks][3], b0, b1);
            }
        }

        __syncwarp();   // prior iteration's PV reads of Ps complete

        // ---- online softmax (2 rows per thread; row = 4 lanes over tig) ----
        #pragma unroll
        for (int u = 0; u < 2; u++) {
            const int qg = qg0 + 8 * u;
            float sv[16];
            float mx = -1e30f;
            #pragma unroll
            for (int nt = 0; nt < 8; nt++) {
                const int kg = kt * 64 + nt * 8 + 2 * tig;
                float2 mv = *(const float2*)(mrow + kg);
                float s0 = sacc[nt][2 * u]     * 0.125f + mv.x;
                float s1 = sacc[nt][2 * u + 1] * 0.125f + mv.y;
                s0 = (kg     <= qg) ? s0 : -1e30f;
                s1 = (kg + 1 <= qg) ? s1 : -1e30f;
                sv[2 * nt] = s0;  sv[2 * nt + 1] = s1;
                mx = fmaxf(mx, fmaxf(s0, s1));
            }
            mx = fmaxf(mx, __shfl_xor_sync(0xffffffffu, mx, 1));
            mx = fmaxf(mx, __shfl_xor_sync(0xffffffffu, mx, 2));
            const float m_new = fmaxf(m_run[u], mx);

            float lsum = 0.f;
            #pragma unroll
            for (int nt = 0; nt < 8; nt++) {
                float p0 = __expf(sv[2 * nt]     - m_new);
                float p1 = __expf(sv[2 * nt + 1] - m_new);
                lsum += p0 + p1;
                float2 pr;
                pr.x = f32_to_tf32(p0);
                pr.y = f32_to_tf32(p1);
                *(float2*)(Ps + (wrow + grp + 8 * u) * FA2_STR + nt * 8 + 2 * tig) = pr;
            }
            lsum += __shfl_xor_sync(0xffffffffu, lsum, 1);
            lsum += __shfl_xor_sync(0xffffffffu, lsum, 2);

            const float alpha = __expf(m_run[u] - m_new);
            l_run[u] = l_run[u] * alpha + lsum;
            m_run[u] = m_new;
            #pragma unroll
            for (int nt = 0; nt < 8; nt++) {
                Oacc[nt][2 * u]     *= alpha;
                Oacc[nt][2 * u + 1] *= alpha;
            }
        }
        __syncwarp();   // P stores visible to this warp's fragment loads

        // ---- O += P @ V  (16 rows x 64 dims per warp) ----
        #pragma unroll
        for (int ks = 0; ks < 8; ks++) {
            const int pb = (wrow + grp) * FA2_STR + ks * 8 + tig;
            uint32_t pa0 = Psu[pb];
            uint32_t pa1 = Psu[pb + 8 * FA2_STR];
            uint32_t pa2 = Psu[pb + 4];
            uint32_t pa3 = Psu[pb + 8 * FA2_STR + 4];
            #pragma unroll
            for (int nt = 0; nt < 8; nt++) {
                const int vb = (ks * 8 + tig) * FA2_STR + nt * 8 + grp;
                uint32_t b0 = Vsu[vb];
                uint32_t b1 = Vsu[vb + 4 * FA2_STR];
                mma16888(Oacc[nt][0], Oacc[nt][1], Oacc[nt][2], Oacc[nt][3],
                         pa0, pa1, pa2, pa3, b0, b1);
            }
        }
    }

    // ---- normalize and write out ----
    #pragma unroll
    for (int u = 0; u < 2; u++) {
        const float inv = 1.f / l_run[u];
        float* dst = g_At + base + (size_t)(qg0 + 8 * u) * D_MODEL;
        #pragma unroll
        for (int nt = 0; nt < 8; nt++) {
            float2 o;
            o.x = Oacc[nt][2 * u]     * inv;
            o.y = Oacc[nt][2 * u + 1] * inv;
            *(float2*)(dst + nt * 8 + 2 * tig) = o;
        }
    }
}

// ============================================================================
// Launch
// ============================================================================
extern "C" void kernel_launch(void* const* d_in, const int* in_sizes, int n_in,
                              void* d_out, int out_size)
{
    const float* q    = (const float*)d_in[0];
    const float* k    = (const float*)d_in[1];
    const float* v    = (const float*)d_in[2];
    const float* mask = (const float*)d_in[3];
    const float* Wq   = (const float*)d_in[4];
    const float* bq   = (const float*)d_in[5];
    const float* Wk   = (const float*)d_in[6];
    const float* bk   = (const float*)d_in[7];
    const float* Wv   = (const float*)d_in[8];
    const float* bv   = (const float*)d_in[9];
    const float* Wp   = (const float*)d_in[10];
    const float* bp   = (const float*)d_in[11];
    float* out = (float*)d_out;

    cudaFuncSetAttribute(flash_attn_mma_kernel,
                         cudaFuncAttributeMaxDynamicSharedMemorySize, FA2_SMEM_BYTES);

    dim3 gg(D_MODEL / 128, MROWS / 128);          // (8, 64)
    mma_gemm_kernel<<<gg, 256>>>(q, Wq, bq, nullptr, 0, 0);
    mma_gemm_kernel<<<gg, 256>>>(k, Wk, bk, nullptr, 0, 1);
    mma_gemm_kernel<<<gg, 256>>>(v, Wv, bv, nullptr, 0, 2);

    dim3 fa_grid(S_LEN / 128, NHEAD, BATCH);      // (16, 16, 4)
    flash_attn_mma_kernel<<<fa_grid, 256, FA2_SMEM_BYTES>>>(mask);

    mma_gemm_kernel<<<gg, 256>>>(nullptr, Wp, bp, out, 1, 3);
}

// round 10
// speedup vs baseline: 5.0736x; 1.1287x over previous
#include <cuda_runtime.h>
#include <cstdint>
#include <math.h>

// Problem constants
#define D_MODEL 1024
#define S_LEN   2048
#define BATCH   4
#define NHEAD   16
#define HDIM    64
#define MROWS   (BATCH * S_LEN)   // 8192

// -------------------- scratch (device globals; no allocation allowed) ------
__device__ float g_Qp[MROWS * D_MODEL];
__device__ float g_Kp[MROWS * D_MODEL];
__device__ float g_Vp[MROWS * D_MODEL];
__device__ float g_At[MROWS * D_MODEL];

__device__ __forceinline__ float f32_to_tf32(float x) {
    uint32_t u;
    asm("cvt.rna.tf32.f32 %0, %1;" : "=r"(u) : "f"(x));
    return __uint_as_float(u);
}
__device__ __forceinline__ void mma16888(float& d0, float& d1, float& d2, float& d3,
                                         uint32_t a0, uint32_t a1, uint32_t a2, uint32_t a3,
                                         uint32_t b0, uint32_t b1) {
    asm volatile(
        "mma.sync.aligned.m16n8k8.row.col.f32.tf32.tf32.f32 "
        "{%0,%1,%2,%3}, {%4,%5,%6,%7}, {%8,%9}, {%0,%1,%2,%3};"
        : "+f"(d0), "+f"(d1), "+f"(d2), "+f"(d3)
        : "r"(a0), "r"(a1), "r"(a2), "r"(a3), "r"(b0), "r"(b1));
}

// ============================================================================
// tf32 tensor-core GEMM body (m16n8k8): C[8192,1024] = A @ W + bias
// 128x128 CTA tile, 8 warps of 64x32, BK=32, 32 chunks. Conflict-free frags.
// ============================================================================
#define GA_STRIDE 36
#define GB_STRIDE 132

__device__ __forceinline__ void gemm_body(
    const float* __restrict__ A, const float* __restrict__ W,
    const float* __restrict__ bias, float* __restrict__ C,
    int bx, int by)
{
    const int N = D_MODEL, K = D_MODEL;
    __shared__ float As[128 * GA_STRIDE];
    __shared__ float Bs[32 * GB_STRIDE];

    const int tid  = threadIdx.x;
    const int wid  = tid >> 5;
    const int lane = tid & 31;
    const int grp  = lane >> 2;
    const int tig  = lane & 3;
    const int wm   = (wid >> 2) * 64;
    const int wn   = (wid & 3) * 32;

    const float* Ag = A + (size_t)by * 128 * K;
    const int arow = tid >> 3;
    const int ac4  = (tid & 7) * 4;
    const int brow = tid >> 5;
    const int bc4  = (tid & 31) * 4;

    float acc[4][4][4];
    #pragma unroll
    for (int mt = 0; mt < 4; mt++)
        #pragma unroll
        for (int nt = 0; nt < 4; nt++)
            #pragma unroll
            for (int c = 0; c < 4; c++) acc[mt][nt][c] = 0.f;

    const uint32_t* Asu = (const uint32_t*)As;
    const uint32_t* Bsu = (const uint32_t*)Bs;

    for (int ch = 0; ch < 32; ch++) {
        const int k0 = ch * 32;
        float4 av[4], bv[4];
        #pragma unroll
        for (int i = 0; i < 4; i++) {
            av[i] = *(const float4*)(Ag + (size_t)(arow + i * 32) * K + k0 + ac4);
            av[i].x = f32_to_tf32(av[i].x);  av[i].y = f32_to_tf32(av[i].y);
            av[i].z = f32_to_tf32(av[i].z);  av[i].w = f32_to_tf32(av[i].w);
            bv[i] = *(const float4*)(W + (size_t)(k0 + brow + i * 8) * N + bx * 128 + bc4);
            bv[i].x = f32_to_tf32(bv[i].x);  bv[i].y = f32_to_tf32(bv[i].y);
            bv[i].z = f32_to_tf32(bv[i].z);  bv[i].w = f32_to_tf32(bv[i].w);
        }
        __syncthreads();
        #pragma unroll
        for (int i = 0; i < 4; i++) {
            *(float4*)(As + (arow + i * 32) * GA_STRIDE + ac4) = av[i];
            *(float4*)(Bs + (brow + i * 8) * GB_STRIDE + bc4)  = bv[i];
        }
        __syncthreads();

        #pragma unroll
        for (int ks = 0; ks < 4; ks++) {
            uint32_t afr[4][4];
            #pragma unroll
            for (int mt = 0; mt < 4; mt++) {
                const int base = (wm + mt * 16 + grp) * GA_STRIDE + ks * 8 + tig;
                afr[mt][0] = Asu[base];
                afr[mt][1] = Asu[base + 8 * GA_STRIDE];
                afr[mt][2] = Asu[base + 4];
                afr[mt][3] = Asu[base + 8 * GA_STRIDE + 4];
            }
            uint32_t bfr[4][2];
            #pragma unroll
            for (int nt = 0; nt < 4; nt++) {
                const int bb = (ks * 8 + tig) * GB_STRIDE + wn + nt * 8 + grp;
                bfr[nt][0] = Bsu[bb];
                bfr[nt][1] = Bsu[bb + 4 * GB_STRIDE];
            }
            #pragma unroll
            for (int mt = 0; mt < 4; mt++)
                #pragma unroll
                for (int nt = 0; nt < 4; nt++)
                    mma16888(acc[mt][nt][0], acc[mt][nt][1],
                             acc[mt][nt][2], acc[mt][nt][3],
                             afr[mt][0], afr[mt][1], afr[mt][2], afr[mt][3],
                             bfr[nt][0], bfr[nt][1]);
        }
    }

    float2 bias2[4];
    #pragma unroll
    for (int nt = 0; nt < 4; nt++)
        bias2[nt] = *(const float2*)(bias + bx * 128 + wn + nt * 8 + tig * 2);

    #pragma unroll
    for (int mt = 0; mt < 4; mt++) {
        const int row = by * 128 + wm + mt * 16 + grp;
        #pragma unroll
        for (int nt = 0; nt < 4; nt++) {
            const int col = bx * 128 + wn + nt * 8 + tig * 2;
            float2 v0, v1;
            v0.x = acc[mt][nt][0] + bias2[nt].x;
            v0.y = acc[mt][nt][1] + bias2[nt].y;
            v1.x = acc[mt][nt][2] + bias2[nt].x;
            v1.y = acc[mt][nt][3] + bias2[nt].y;
            *(float2*)(C + (size_t)row * N + col)       = v0;
            *(float2*)(C + (size_t)(row + 8) * N + col) = v1;
        }
    }
}

// Fused Q/K/V projection: blockIdx.z selects (input, W, bias, dst).
__global__ void __launch_bounds__(256, 2) mma_gemm_qkv_kernel(
    const float* __restrict__ q, const float* __restrict__ k,
    const float* __restrict__ v,
    const float* __restrict__ Wq, const float* __restrict__ Wk,
    const float* __restrict__ Wv,
    const float* __restrict__ bq, const float* __restrict__ bk,
    const float* __restrict__ bv)
{
    const int z = blockIdx.z;
    const float* A    = (z == 0) ? q  : (z == 1) ? k  : v;
    const float* W    = (z == 0) ? Wq : (z == 1) ? Wk : Wv;
    const float* bias = (z == 0) ? bq : (z == 1) ? bk : bv;
    float* C          = (z == 0) ? g_Qp : (z == 1) ? g_Kp : g_Vp;
    gemm_body(A, W, bias, C, blockIdx.x, blockIdx.y);
}

// Output projection: reads g_At, writes external out.
__global__ void __launch_bounds__(256, 2) mma_gemm_out_kernel(
    const float* __restrict__ W, const float* __restrict__ bias,
    float* __restrict__ out)
{
    gemm_body(g_At, W, bias, out, blockIdx.x, blockIdx.y);
}

// ============================================================================
// Flash attention with mma.sync tf32 (causal). Block = (128 q-rows, head, b).
// 8 warps; warp w owns q-rows [16w, 16w+16). Q frags in registers; K/V 64x64
// smem tiles (stride 68, tf32-rounded). __launch_bounds__(256,2) caps at
// 128 regs -> 2 CTAs/SM (vs 1 before: the round-8 latency bottleneck).
// ============================================================================
#define FA2_STR 68
#define FA2_SMEM_BYTES ((64 * FA2_STR + 64 * FA2_STR + 128 * FA2_STR) * 4)

__global__ void __launch_bounds__(256, 2) flash_attn_mma_kernel(
    const float* __restrict__ mask)
{
    extern __shared__ float sm[];
    float* Ks = sm;                       // [64][68]
    float* Vs = Ks + 64 * FA2_STR;        // [64][68]
    float* Ps = Vs + 64 * FA2_STR;        // [128][68]
    const uint32_t* Ksu = (const uint32_t*)Ks;
    const uint32_t* Vsu = (const uint32_t*)Vs;
    const uint32_t* Psu = (const uint32_t*)Ps;

    const int qt  = (int)gridDim.x - 1 - (int)blockIdx.x;  // heavy tiles first
    const int h   = blockIdx.y;
    const int b   = blockIdx.z;
    const int tid = threadIdx.x;
    const int wid = tid >> 5, lane = tid & 31;
    const int grp = lane >> 2, tig = lane & 3;
    const int wrow = wid * 16;

    const size_t base = ((size_t)b * S_LEN) * D_MODEL + h * HDIM;
    const float* mrow = mask + (size_t)b * S_LEN;

    // ---- Q fragments in registers (reused for every k-tile) ----
    uint32_t qa[8][4];
    {
        const float* Qg = g_Qp + base + (size_t)(qt * 128 + wrow) * D_MODEL;
        #pragma unroll
        for (int ks = 0; ks < 8; ks++) {
            qa[ks][0] = __float_as_uint(f32_to_tf32(Qg[(size_t)grp       * D_MODEL + ks * 8 + tig]));
            qa[ks][1] = __float_as_uint(f32_to_tf32(Qg[(size_t)(grp + 8) * D_MODEL + ks * 8 + tig]));
            qa[ks][2] = __float_as_uint(f32_to_tf32(Qg[(size_t)grp       * D_MODEL + ks * 8 + tig + 4]));
            qa[ks][3] = __float_as_uint(f32_to_tf32(Qg[(size_t)(grp + 8) * D_MODEL + ks * 8 + tig + 4]));
        }
    }

    float Oacc[8][4];
    #pragma unroll
    for (int nt = 0; nt < 8; nt++)
        #pragma unroll
        for (int c = 0; c < 4; c++) Oacc[nt][c] = 0.f;
    float m_run[2] = {-1e30f, -1e30f};
    float l_run[2] = {0.f, 0.f};

    const int qg0 = qt * 128 + wrow + grp;   // row for u=0 (u=1: +8)
    const int ntiles = 2 * qt + 2;

    for (int kt = 0; kt < ntiles; kt++) {
        __syncthreads();     // all warps done with previous K/V tiles
        {
            const int lr = tid >> 2;            // 0..63
            const int lc = (tid & 3) * 16;
            const float* ksrc = g_Kp + base + (size_t)(kt * 64 + lr) * D_MODEL + lc;
            const float* vsrc = g_Vp + base + (size_t)(kt * 64 + lr) * D_MODEL + lc;
            float* kdst = Ks + lr * FA2_STR + lc;
            float* vdst = Vs + lr * FA2_STR + lc;
            #pragma unroll
            for (int j = 0; j < 4; j++) {
                float4 kv = *(const float4*)(ksrc + 4 * j);
                kv.x = f32_to_tf32(kv.x);  kv.y = f32_to_tf32(kv.y);
                kv.z = f32_to_tf32(kv.z);  kv.w = f32_to_tf32(kv.w);
                *(float4*)(kdst + 4 * j) = kv;
                float4 vv = *(const float4*)(vsrc + 4 * j);
                vv.x = f32_to_tf32(vv.x);  vv.y = f32_to_tf32(vv.y);
                vv.z = f32_to_tf32(vv.z);  vv.w = f32_to_tf32(vv.w);
                *(float4*)(vdst + 4 * j) = vv;
            }
        }
        __syncthreads();

        // ---- scores S = Q @ K^T  (16 rows x 64 keys per warp) ----
        float sacc[8][4];
        #pragma unroll
        for (int nt = 0; nt < 8; nt++)
            #pragma unroll
            for (int c = 0; c < 4; c++) sacc[nt][c] = 0.f;

        #pragma unroll
        for (int ks = 0; ks < 8; ks++) {
            #pragma unroll
            for (int nt = 0; nt < 8; nt++) {
                const int bb = (nt * 8 + grp) * FA2_STR + ks * 8 + tig;
                uint32_t b0 = Ksu[bb];
                uint32_t b1 = Ksu[bb + 4];
                mma16888(sacc[nt][0], sacc[nt][1], sacc[nt][2], sacc[nt][3],
                         qa[ks][0], qa[ks][1], qa[ks][2], qa[ks][3], b0, b1);
            }
        }

        __syncwarp();   // prior iteration's PV reads of Ps complete

        // ---- online softmax (2 rows/thread; mask+scale in place in sacc) ----
        #pragma unroll
        for (int u = 0; u < 2; u++) {
            const int qg = qg0 + 8 * u;
            float mx = -1e30f;
            #pragma unroll
            for (int nt = 0; nt < 8; nt++) {
                const int kg = kt * 64 + nt * 8 + 2 * tig;
                float2 mv = *(const float2*)(mrow + kg);
                float s0 = sacc[nt][2 * u]     * 0.125f + mv.x;
                float s1 = sacc[nt][2 * u + 1] * 0.125f + mv.y;
                s0 = (kg     <= qg) ? s0 : -1e30f;
                s1 = (kg + 1 <= qg) ? s1 : -1e30f;
                sacc[nt][2 * u]     = s0;
                sacc[nt][2 * u + 1] = s1;
                mx = fmaxf(mx, fmaxf(s0, s1));
            }
            mx = fmaxf(mx, __shfl_xor_sync(0xffffffffu, mx, 1));
            mx = fmaxf(mx, __shfl_xor_sync(0xffffffffu, mx, 2));
            const float m_new = fmaxf(m_run[u], mx);

            float lsum = 0.f;
            #pragma unroll
            for (int nt = 0; nt < 8; nt++) {
                float p0 = __expf(sacc[nt][2 * u]     - m_new);
                float p1 = __expf(sacc[nt][2 * u + 1] - m_new);
                lsum += p0 + p1;
                float2 pr;
                pr.x = f32_to_tf32(p0);
                pr.y = f32_to_tf32(p1);
                *(float2*)(Ps + (wrow + grp + 8 * u) * FA2_STR + nt * 8 + 2 * tig) = pr;
            }
            lsum += __shfl_xor_sync(0xffffffffu, lsum, 1);
            lsum += __shfl_xor_sync(0xffffffffu, lsum, 2);

            const float alpha = __expf(m_run[u] - m_new);
            l_run[u] = l_run[u] * alpha + lsum;
            m_run[u] = m_new;
            #pragma unroll
            for (int nt = 0; nt < 8; nt++) {
                Oacc[nt][2 * u]     *= alpha;
                Oacc[nt][2 * u + 1] *= alpha;
            }
        }
        __syncwarp();   // P stores visible to this warp's fragment loads

        // ---- O += P @ V  (16 rows x 64 dims per warp) ----
        #pragma unroll
        for (int ks = 0; ks < 8; ks++) {
            const int pb = (wrow + grp) * FA2_STR + ks * 8 + tig;
            uint32_t pa0 = Psu[pb];
            uint32_t pa1 = Psu[pb + 8 * FA2_STR];
            uint32_t pa2 = Psu[pb + 4];
            uint32_t pa3 = Psu[pb + 8 * FA2_STR + 4];
            #pragma unroll
            for (int nt = 0; nt < 8; nt++) {
                const int vb = (ks * 8 + tig) * FA2_STR + nt * 8 + grp;
                uint32_t b0 = Vsu[vb];
                uint32_t b1 = Vsu[vb + 4 * FA2_STR];
                mma16888(Oacc[nt][0], Oacc[nt][1], Oacc[nt][2], Oacc[nt][3],
                         pa0, pa1, pa2, pa3, b0, b1);
            }
        }
    }

    // ---- normalize and write out ----
    #pragma unroll
    for (int u = 0; u < 2; u++) {
        const float inv = 1.f / l_run[u];
        float* dst = g_At + base + (size_t)(qg0 + 8 * u) * D_MODEL;
        #pragma unroll
        for (int nt = 0; nt < 8; nt++) {
            float2 o;
            o.x = Oacc[nt][2 * u]     * inv;
            o.y = Oacc[nt][2 * u + 1] * inv;
            *(float2*)(dst + nt * 8 + 2 * tig) = o;
        }
    }
}

// ============================================================================
// Launch
// ============================================================================
extern "C" void kernel_launch(void* const* d_in, const int* in_sizes, int n_in,
                              void* d_out, int out_size)
{
    const float* q    = (const float*)d_in[0];
    const float* k    = (const float*)d_in[1];
    const float* v    = (const float*)d_in[2];
    const float* mask = (const float*)d_in[3];
    const float* Wq   = (const float*)d_in[4];
    const float* bq   = (const float*)d_in[5];
    const float* Wk   = (const float*)d_in[6];
    const float* bk   = (const float*)d_in[7];
    const float* Wv   = (const float*)d_in[8];
    const float* bv   = (const float*)d_in[9];
    const float* Wp   = (const float*)d_in[10];
    const float* bp   = (const float*)d_in[11];
    float* out = (float*)d_out;

    cudaFuncSetAttribute(flash_attn_mma_kernel,
                         cudaFuncAttributeMaxDynamicSharedMemorySize, FA2_SMEM_BYTES);

    dim3 gqkv(D_MODEL / 128, MROWS / 128, 3);     // (8, 64, 3) fused QKV
    mma_gemm_qkv_kernel<<<gqkv, 256>>>(q, k, v, Wq, Wk, Wv, bq, bk, bv);

    dim3 fa_grid(S_LEN / 128, NHEAD, BATCH);      // (16, 16, 4)
    flash_attn_mma_kernel<<<fa_grid, 256, FA2_SMEM_BYTES>>>(mask);

    dim3 gg(D_MODEL / 128, MROWS / 128);          // (8, 64)
    mma_gemm_out_kernel<<<gg, 256>>>(Wp, bp, out);
}

// round 11
// speedup vs baseline: 5.3399x; 1.0525x over previous
#include <cuda_runtime.h>
#include <cstdint>
#include <math.h>

// Problem constants
#define D_MODEL 1024
#define S_LEN   2048
#define BATCH   4
#define NHEAD   16
#define HDIM    64
#define MROWS   (BATCH * S_LEN)   // 8192

// -------------------- scratch (device globals; no allocation allowed) ------
__device__ float g_Qp[MROWS * D_MODEL];   // tf32-rounded projected Q
__device__ float g_Kp[MROWS * D_MODEL];   // tf32-rounded projected K
__device__ float g_Vp[MROWS * D_MODEL];   // tf32-rounded projected V
__device__ float g_At[MROWS * D_MODEL];   // attention output (full fp32)

__device__ __forceinline__ float f32_to_tf32(float x) {
    uint32_t u;
    asm("cvt.rna.tf32.f32 %0, %1;" : "=r"(u) : "f"(x));
    return __uint_as_float(u);
}
__device__ __forceinline__ void mma16888(float& d0, float& d1, float& d2, float& d3,
                                         uint32_t a0, uint32_t a1, uint32_t a2, uint32_t a3,
                                         uint32_t b0, uint32_t b1) {
    asm volatile(
        "mma.sync.aligned.m16n8k8.row.col.f32.tf32.tf32.f32 "
        "{%0,%1,%2,%3}, {%4,%5,%6,%7}, {%8,%9}, {%0,%1,%2,%3};"
        : "+f"(d0), "+f"(d1), "+f"(d2), "+f"(d3)
        : "r"(a0), "r"(a1), "r"(a2), "r"(a3), "r"(b0), "r"(b1));
}
#define CP_ASYNC16(dst32, srcp) \
    asm volatile("cp.async.cg.shared.global [%0], [%1], 16;" \
                 :: "r"(dst32), "l"(srcp) : "memory")
#define CP_COMMIT() asm volatile("cp.async.commit_group;" ::: "memory")
#define CP_WAIT0()  asm volatile("cp.async.wait_group 0;" ::: "memory")

// ============================================================================
// tf32 tensor-core GEMM body (m16n8k8): C[8192,1024] = A @ W + bias
// 128x128 CTA tile, 8 warps of 64x32, BK=32, 32 chunks. Conflict-free frags.
// round_c: tf32-RN-round outputs (for Q/K/V so flash can raw-copy them).
// ============================================================================
#define GA_STRIDE 36
#define GB_STRIDE 132

__device__ __forceinline__ void gemm_body(
    const float* __restrict__ A, const float* __restrict__ W,
    const float* __restrict__ bias, float* __restrict__ C,
    int bx, int by, bool round_c)
{
    const int N = D_MODEL, K = D_MODEL;
    __shared__ float As[128 * GA_STRIDE];
    __shared__ float Bs[32 * GB_STRIDE];

    const int tid  = threadIdx.x;
    const int wid  = tid >> 5;
    const int lane = tid & 31;
    const int grp  = lane >> 2;
    const int tig  = lane & 3;
    const int wm   = (wid >> 2) * 64;
    const int wn   = (wid & 3) * 32;

    const float* Ag = A + (size_t)by * 128 * K;
    const int arow = tid >> 3;
    const int ac4  = (tid & 7) * 4;
    const int brow = tid >> 5;
    const int bc4  = (tid & 31) * 4;

    float acc[4][4][4];
    #pragma unroll
    for (int mt = 0; mt < 4; mt++)
        #pragma unroll
        for (int nt = 0; nt < 4; nt++)
            #pragma unroll
            for (int c = 0; c < 4; c++) acc[mt][nt][c] = 0.f;

    const uint32_t* Asu = (const uint32_t*)As;
    const uint32_t* Bsu = (const uint32_t*)Bs;

    for (int ch = 0; ch < 32; ch++) {
        const int k0 = ch * 32;
        float4 av[4], bv[4];
        #pragma unroll
        for (int i = 0; i < 4; i++) {
            av[i] = *(const float4*)(Ag + (size_t)(arow + i * 32) * K + k0 + ac4);
            av[i].x = f32_to_tf32(av[i].x);  av[i].y = f32_to_tf32(av[i].y);
            av[i].z = f32_to_tf32(av[i].z);  av[i].w = f32_to_tf32(av[i].w);
            bv[i] = *(const float4*)(W + (size_t)(k0 + brow + i * 8) * N + bx * 128 + bc4);
            bv[i].x = f32_to_tf32(bv[i].x);  bv[i].y = f32_to_tf32(bv[i].y);
            bv[i].z = f32_to_tf32(bv[i].z);  bv[i].w = f32_to_tf32(bv[i].w);
        }
        __syncthreads();
        #pragma unroll
        for (int i = 0; i < 4; i++) {
            *(float4*)(As + (arow + i * 32) * GA_STRIDE + ac4) = av[i];
            *(float4*)(Bs + (brow + i * 8) * GB_STRIDE + bc4)  = bv[i];
        }
        __syncthreads();

        #pragma unroll
        for (int ks = 0; ks < 4; ks++) {
            uint32_t afr[4][4];
            #pragma unroll
            for (int mt = 0; mt < 4; mt++) {
                const int base = (wm + mt * 16 + grp) * GA_STRIDE + ks * 8 + tig;
                afr[mt][0] = Asu[base];
                afr[mt][1] = Asu[base + 8 * GA_STRIDE];
                afr[mt][2] = Asu[base + 4];
                afr[mt][3] = Asu[base + 8 * GA_STRIDE + 4];
            }
            uint32_t bfr[4][2];
            #pragma unroll
            for (int nt = 0; nt < 4; nt++) {
                const int bb = (ks * 8 + tig) * GB_STRIDE + wn + nt * 8 + grp;
                bfr[nt][0] = Bsu[bb];
                bfr[nt][1] = Bsu[bb + 4 * GB_STRIDE];
            }
            #pragma unroll
            for (int mt = 0; mt < 4; mt++)
                #pragma unroll
                for (int nt = 0; nt < 4; nt++)
                    mma16888(acc[mt][nt][0], acc[mt][nt][1],
                             acc[mt][nt][2], acc[mt][nt][3],
                             afr[mt][0], afr[mt][1], afr[mt][2], afr[mt][3],
                             bfr[nt][0], bfr[nt][1]);
        }
    }

    float2 bias2[4];
    #pragma unroll
    for (int nt = 0; nt < 4; nt++)
        bias2[nt] = *(const float2*)(bias + bx * 128 + wn + nt * 8 + tig * 2);

    #pragma unroll
    for (int mt = 0; mt < 4; mt++) {
        const int row = by * 128 + wm + mt * 16 + grp;
        #pragma unroll
        for (int nt = 0; nt < 4; nt++) {
            const int col = bx * 128 + wn + nt * 8 + tig * 2;
            float2 v0, v1;
            v0.x = acc[mt][nt][0] + bias2[nt].x;
            v0.y = acc[mt][nt][1] + bias2[nt].y;
            v1.x = acc[mt][nt][2] + bias2[nt].x;
            v1.y = acc[mt][nt][3] + bias2[nt].y;
            if (round_c) {
                v0.x = f32_to_tf32(v0.x);  v0.y = f32_to_tf32(v0.y);
                v1.x = f32_to_tf32(v1.x);  v1.y = f32_to_tf32(v1.y);
            }
            *(float2*)(C + (size_t)row * N + col)       = v0;
            *(float2*)(C + (size_t)(row + 8) * N + col) = v1;
        }
    }
}

// Fused Q/K/V projection: blockIdx.z selects (input, W, bias, dst).
__global__ void __launch_bounds__(256, 2) mma_gemm_qkv_kernel(
    const float* __restrict__ q, const float* __restrict__ k,
    const float* __restrict__ v,
    const float* __restrict__ Wq, const float* __restrict__ Wk,
    const float* __restrict__ Wv,
    const float* __restrict__ bq, const float* __restrict__ bk,
    const float* __restrict__ bv)
{
    const int z = blockIdx.z;
    const float* A    = (z == 0) ? q  : (z == 1) ? k  : v;
    const float* W    = (z == 0) ? Wq : (z == 1) ? Wk : Wv;
    const float* bias = (z == 0) ? bq : (z == 1) ? bk : bv;
    float* C          = (z == 0) ? g_Qp : (z == 1) ? g_Kp : g_Vp;
    gemm_body(A, W, bias, C, blockIdx.x, blockIdx.y, true);   // pre-rounded
}

// Output projection: reads g_At, writes external out (NOT rounded).
__global__ void __launch_bounds__(256, 2) mma_gemm_out_kernel(
    const float* __restrict__ W, const float* __restrict__ bias,
    float* __restrict__ out)
{
    gemm_body(g_At, W, bias, out, blockIdx.x, blockIdx.y, false);
}

// ============================================================================
// Flash attention, mma.sync tf32, cp.async double-buffered K/V (causal).
// Block = (128 q-rows, head, batch), 8 warps x 16 q-rows. Q frags in regs.
// K/V ping-pong buffers filled by cp.async.cg (inputs pre-rounded to tf32 in
// the projection epilogue, so raw byte copies are exact). One __syncthreads
// per k-tile; next tile's loads overlap with current tile's compute.
// ============================================================================
#define FA3_STR 68
#define FA3_KV  (64 * FA3_STR)
#define FA3_SMEM_BYTES ((4 * FA3_KV + 128 * FA3_STR) * 4)   // 104448 B

__global__ void __launch_bounds__(256, 2) flash_attn_mma_kernel(
    const float* __restrict__ mask)
{
    extern __shared__ float sm[];
    // layout: K0 | V0 | K1 | V1 | P
    float* Ps = sm + 4 * FA3_KV;
    const uint32_t* Psu = (const uint32_t*)Ps;
    const uint32_t smbase = (uint32_t)__cvta_generic_to_shared(sm);

    const int qt  = (int)gridDim.x - 1 - (int)blockIdx.x;  // heavy tiles first
    const int h   = blockIdx.y;
    const int b   = blockIdx.z;
    const int tid = threadIdx.x;
    const int wid = tid >> 5, lane = tid & 31;
    const int grp = lane >> 2, tig = lane & 3;
    const int wrow = wid * 16;

    const size_t base = ((size_t)b * S_LEN) * D_MODEL + h * HDIM;
    const float* mrow = mask + (size_t)b * S_LEN;

    // per-thread staging slots (row lr, 16-float col block lc)
    const int lr = tid >> 2;            // 0..63
    const int lc = (tid & 3) * 16;
    const float* kgbase = g_Kp + base + (size_t)lr * D_MODEL + lc;
    const float* vgbase = g_Vp + base + (size_t)lr * D_MODEL + lc;
    const uint32_t kslot = smbase + (uint32_t)((lr * FA3_STR + lc) * 4);
    const uint32_t vslot = kslot + (uint32_t)(FA3_KV * 4);

    // ---- Q fragments in registers (g_Qp already tf32-rounded) ----
    uint32_t qa[8][4];
    {
        const float* Qg = g_Qp + base + (size_t)(qt * 128 + wrow) * D_MODEL;
        #pragma unroll
        for (int ks = 0; ks < 8; ks++) {
            qa[ks][0] = __float_as_uint(Qg[(size_t)grp       * D_MODEL + ks * 8 + tig]);
            qa[ks][1] = __float_as_uint(Qg[(size_t)(grp + 8) * D_MODEL + ks * 8 + tig]);
            qa[ks][2] = __float_as_uint(Qg[(size_t)grp       * D_MODEL + ks * 8 + tig + 4]);
            qa[ks][3] = __float_as_uint(Qg[(size_t)(grp + 8) * D_MODEL + ks * 8 + tig + 4]);
        }
    }

    float Oacc[8][4];
    #pragma unroll
    for (int nt = 0; nt < 8; nt++)
        #pragma unroll
        for (int c = 0; c < 4; c++) Oacc[nt][c] = 0.f;
    float m_run[2] = {-1e30f, -1e30f};
    float l_run[2] = {0.f, 0.f};

    const int qg0 = qt * 128 + wrow + grp;   // row for u=0 (u=1: +8)
    const int ntiles = 2 * qt + 2;

    // prologue: tile 0 into buffer 0
    {
        const float* ks0 = kgbase;
        const float* vs0 = vgbase;
        #pragma unroll
        for (int j = 0; j < 4; j++) {
            CP_ASYNC16(kslot + 16 * j, ks0 + 4 * j);
            CP_ASYNC16(vslot + 16 * j, vs0 + 4 * j);
        }
        CP_COMMIT();
    }

    for (int kt = 0; kt < ntiles; kt++) {
        const int cur = kt & 1;
        CP_WAIT0();          // tile kt's copies done (issuing thread)
        __syncthreads();     // visible to all; prev compute done -> other buf free

        if (kt + 1 < ntiles) {
            const uint32_t off = (uint32_t)((1 - cur) * 2 * FA3_KV * 4);
            const float* ksn = kgbase + (size_t)(kt + 1) * 64 * D_MODEL;
            const float* vsn = vgbase + (size_t)(kt + 1) * 64 * D_MODEL;
            #pragma unroll
            for (int j = 0; j < 4; j++) {
                CP_ASYNC16(kslot + off + 16 * j, ksn + 4 * j);
                CP_ASYNC16(vslot + off + 16 * j, vsn + 4 * j);
            }
            CP_COMMIT();
        }

        const uint32_t* Ksu = (const uint32_t*)(sm + cur * 2 * FA3_KV);
        const uint32_t* Vsu = Ksu + FA3_KV;

        // ---- scores S = Q @ K^T  (16 rows x 64 keys per warp) ----
        float sacc[8][4];
        #pragma unroll
        for (int nt = 0; nt < 8; nt++)
            #pragma unroll
            for (int c = 0; c < 4; c++) sacc[nt][c] = 0.f;

        #pragma unroll
        for (int ks = 0; ks < 8; ks++) {
            #pragma unroll
            for (int nt = 0; nt < 8; nt++) {
                const int bb = (nt * 8 + grp) * FA3_STR + ks * 8 + tig;
                uint32_t b0 = Ksu[bb];
                uint32_t b1 = Ksu[bb + 4];
                mma16888(sacc[nt][0], sacc[nt][1], sacc[nt][2], sacc[nt][3],
                         qa[ks][0], qa[ks][1], qa[ks][2], qa[ks][3], b0, b1);
            }
        }

        __syncwarp();   // prior iteration's PV reads of Ps complete

        // ---- online softmax (2 rows/thread; mask+scale in place) ----
        #pragma unroll
        for (int u = 0; u < 2; u++) {
            const int qg = qg0 + 8 * u;
            float mx = -1e30f;
            #pragma unroll
            for (int nt = 0; nt < 8; nt++) {
                const int kg = kt * 64 + nt * 8 + 2 * tig;
                float2 mv = *(const float2*)(mrow + kg);
                float s0 = sacc[nt][2 * u]     * 0.125f + mv.x;
                float s1 = sacc[nt][2 * u + 1] * 0.125f + mv.y;
                s0 = (kg     <= qg) ? s0 : -1e30f;
                s1 = (kg + 1 <= qg) ? s1 : -1e30f;
                sacc[nt][2 * u]     = s0;
                sacc[nt][2 * u + 1] = s1;
                mx = fmaxf(mx, fmaxf(s0, s1));
            }
            mx = fmaxf(mx, __shfl_xor_sync(0xffffffffu, mx, 1));
            mx = fmaxf(mx, __shfl_xor_sync(0xffffffffu, mx, 2));
            const float m_new = fmaxf(m_run[u], mx);

            float lsum = 0.f;
            #pragma unroll
            for (int nt = 0; nt < 8; nt++) {
                float p0 = __expf(sacc[nt][2 * u]     - m_new);
                float p1 = __expf(sacc[nt][2 * u + 1] - m_new);
                lsum += p0 + p1;
                float2 pr;
                pr.x = f32_to_tf32(p0);
                pr.y = f32_to_tf32(p1);
                *(float2*)(Ps + (wrow + grp + 8 * u) * FA3_STR + nt * 8 + 2 * tig) = pr;
            }
            lsum += __shfl_xor_sync(0xffffffffu, lsum, 1);
            lsum += __shfl_xor_sync(0xffffffffu, lsum, 2);

            const float alpha = __expf(m_run[u] - m_new);
            l_run[u] = l_run[u] * alpha + lsum;
            m_run[u] = m_new;
            #pragma unroll
            for (int nt = 0; nt < 8; nt++) {
                Oacc[nt][2 * u]     *= alpha;
                Oacc[nt][2 * u + 1] *= alpha;
            }
        }
        __syncwarp();   // P stores visible to this warp's fragment loads

        // ---- O += P @ V  (16 rows x 64 dims per warp) ----
        #pragma unroll
        for (int ks = 0; ks < 8; ks++) {
            const int pb = (wrow + grp) * FA3_STR + ks * 8 + tig;
            uint32_t pa0 = Psu[pb];
            uint32_t pa1 = Psu[pb + 8 * FA3_STR];
            uint32_t pa2 = Psu[pb + 4];
            uint32_t pa3 = Psu[pb + 8 * FA3_STR + 4];
            #pragma unroll
            for (int nt = 0; nt < 8; nt++) {
                const int vb = (ks * 8 + tig) * FA3_STR + nt * 8 + grp;
                uint32_t b0 = Vsu[vb];
                uint32_t b1 = Vsu[vb + 4 * FA3_STR];
                mma16888(Oacc[nt][0], Oacc[nt][1], Oacc[nt][2], Oacc[nt][3],
                         pa0, pa1, pa2, pa3, b0, b1);
            }
        }
    }

    // ---- normalize and write out ----
    #pragma unroll
    for (int u = 0; u < 2; u++) {
        const float inv = 1.f / l_run[u];
        float* dst = g_At + base + (size_t)(qg0 + 8 * u) * D_MODEL;
        #pragma unroll
        for (int nt = 0; nt < 8; nt++) {
            float2 o;
            o.x = Oacc[nt][2 * u]     * inv;
            o.y = Oacc[nt][2 * u + 1] * inv;
            *(float2*)(dst + nt * 8 + 2 * tig) = o;
        }
    }
}

// ============================================================================
// Launch
// ============================================================================
extern "C" void kernel_launch(void* const* d_in, const int* in_sizes, int n_in,
                              void* d_out, int out_size)
{
    const float* q    = (const float*)d_in[0];
    const float* k    = (const float*)d_in[1];
    const float* v    = (const float*)d_in[2];
    const float* mask = (const float*)d_in[3];
    const float* Wq   = (const float*)d_in[4];
    const float* bq   = (const float*)d_in[5];
    const float* Wk   = (const float*)d_in[6];
    const float* bk   = (const float*)d_in[7];
    const float* Wv   = (const float*)d_in[8];
    const float* bv   = (const float*)d_in[9];
    const float* Wp   = (const float*)d_in[10];
    const float* bp   = (const float*)d_in[11];
    float* out = (float*)d_out;

    cudaFuncSetAttribute(flash_attn_mma_kernel,
                         cudaFuncAttributeMaxDynamicSharedMemorySize, FA3_SMEM_BYTES);

    dim3 gqkv(D_MODEL / 128, MROWS / 128, 3);     // (8, 64, 3) fused QKV
    mma_gemm_qkv_kernel<<<gqkv, 256>>>(q, k, v, Wq, Wk, Wv, bq, bk, bv);

    dim3 fa_grid(S_LEN / 128, NHEAD, BATCH);      // (16, 16, 4)
    flash_attn_mma_kernel<<<fa_grid, 256, FA3_SMEM_BYTES>>>(mask);

    dim3 gg(D_MODEL / 128, MROWS / 128);          // (8, 64)
    mma_gemm_out_kernel<<<gg, 256>>>(Wp, bp, out);
}

// round 12
// speedup vs baseline: 5.6443x; 1.0570x over previous
#include <cuda_runtime.h>
#include <cstdint>
#include <math.h>

// Problem constants
#define D_MODEL 1024
#define S_LEN   2048
#define BATCH   4
#define NHEAD   16
#define HDIM    64
#define MROWS   (BATCH * S_LEN)   // 8192

// -------------------- scratch (device globals; no allocation allowed) ------
__device__ float g_Qp[MROWS * D_MODEL];   // tf32-rounded projected Q
__device__ float g_Kp[MROWS * D_MODEL];   // tf32-rounded projected K
__device__ float g_Vp[MROWS * D_MODEL];   // tf32-rounded projected V [b][s][d]
__device__ float g_Vt[MROWS * D_MODEL];   // V transposed  [b][dim][s]
__device__ float g_At[MROWS * D_MODEL];   // attention output (full fp32)

__device__ __forceinline__ float f32_to_tf32(float x) {
    uint32_t u;
    asm("cvt.rna.tf32.f32 %0, %1;" : "=r"(u) : "f"(x));
    return __uint_as_float(u);
}
__device__ __forceinline__ void mma16888(float& d0, float& d1, float& d2, float& d3,
                                         uint32_t a0, uint32_t a1, uint32_t a2, uint32_t a3,
                                         uint32_t b0, uint32_t b1) {
    asm volatile(
        "mma.sync.aligned.m16n8k8.row.col.f32.tf32.tf32.f32 "
        "{%0,%1,%2,%3}, {%4,%5,%6,%7}, {%8,%9}, {%0,%1,%2,%3};"
        : "+f"(d0), "+f"(d1), "+f"(d2), "+f"(d3)
        : "r"(a0), "r"(a1), "r"(a2), "r"(a3), "r"(b0), "r"(b1));
}
#define LDMATRIX_X4(r0, r1, r2, r3, addr) \
    asm volatile("ldmatrix.sync.aligned.m8n8.x4.shared.b16 {%0,%1,%2,%3}, [%4];" \
                 : "=r"(r0), "=r"(r1), "=r"(r2), "=r"(r3) : "r"(addr))
#define CP_ASYNC16(dst32, srcp) \
    asm volatile("cp.async.cg.shared.global [%0], [%1], 16;" \
                 :: "r"(dst32), "l"(srcp) : "memory")
#define CP_COMMIT() asm volatile("cp.async.commit_group;" ::: "memory")
#define CP_WAIT0()  asm volatile("cp.async.wait_group 0;" ::: "memory")

// ============================================================================
// tf32 tensor-core GEMM body (m16n8k8)  [unchanged — at its reuse-ratio limit]
// ============================================================================
#define GA_STRIDE 36
#define GB_STRIDE 132

__device__ __forceinline__ void gemm_body(
    const float* __restrict__ A, const float* __restrict__ W,
    const float* __restrict__ bias, float* __restrict__ C,
    int bx, int by, bool round_c)
{
    const int N = D_MODEL, K = D_MODEL;
    __shared__ float As[128 * GA_STRIDE];
    __shared__ float Bs[32 * GB_STRIDE];

    const int tid  = threadIdx.x;
    const int wid  = tid >> 5;
    const int lane = tid & 31;
    const int grp  = lane >> 2;
    const int tig  = lane & 3;
    const int wm   = (wid >> 2) * 64;
    const int wn   = (wid & 3) * 32;

    const float* Ag = A + (size_t)by * 128 * K;
    const int arow = tid >> 3;
    const int ac4  = (tid & 7) * 4;
    const int brow = tid >> 5;
    const int bc4  = (tid & 31) * 4;

    float acc[4][4][4];
    #pragma unroll
    for (int mt = 0; mt < 4; mt++)
        #pragma unroll
        for (int nt = 0; nt < 4; nt++)
            #pragma unroll
            for (int c = 0; c < 4; c++) acc[mt][nt][c] = 0.f;

    const uint32_t* Asu = (const uint32_t*)As;
    const uint32_t* Bsu = (const uint32_t*)Bs;

    for (int ch = 0; ch < 32; ch++) {
        const int k0 = ch * 32;
        float4 av[4], bv[4];
        #pragma unroll
        for (int i = 0; i < 4; i++) {
            av[i] = *(const float4*)(Ag + (size_t)(arow + i * 32) * K + k0 + ac4);
            av[i].x = f32_to_tf32(av[i].x);  av[i].y = f32_to_tf32(av[i].y);
            av[i].z = f32_to_tf32(av[i].z);  av[i].w = f32_to_tf32(av[i].w);
            bv[i] = *(const float4*)(W + (size_t)(k0 + brow + i * 8) * N + bx * 128 + bc4);
            bv[i].x = f32_to_tf32(bv[i].x);  bv[i].y = f32_to_tf32(bv[i].y);
            bv[i].z = f32_to_tf32(bv[i].z);  bv[i].w = f32_to_tf32(bv[i].w);
        }
        __syncthreads();
        #pragma unroll
        for (int i = 0; i < 4; i++) {
            *(float4*)(As + (arow + i * 32) * GA_STRIDE + ac4) = av[i];
            *(float4*)(Bs + (brow + i * 8) * GB_STRIDE + bc4)  = bv[i];
        }
        __syncthreads();

        #pragma unroll
        for (int ks = 0; ks < 4; ks++) {
            uint32_t afr[4][4];
            #pragma unroll
            for (int mt = 0; mt < 4; mt++) {
                const int base = (wm + mt * 16 + grp) * GA_STRIDE + ks * 8 + tig;
                afr[mt][0] = Asu[base];
                afr[mt][1] = Asu[base + 8 * GA_STRIDE];
                afr[mt][2] = Asu[base + 4];
                afr[mt][3] = Asu[base + 8 * GA_STRIDE + 4];
            }
            uint32_t bfr[4][2];
            #pragma unroll
            for (int nt = 0; nt < 4; nt++) {
                const int bb = (ks * 8 + tig) * GB_STRIDE + wn + nt * 8 + grp;
                bfr[nt][0] = Bsu[bb];
                bfr[nt][1] = Bsu[bb + 4 * GB_STRIDE];
            }
            #pragma unroll
            for (int mt = 0; mt < 4; mt++)
                #pragma unroll
                for (int nt = 0; nt < 4; nt++)
                    mma16888(acc[mt][nt][0], acc[mt][nt][1],
                             acc[mt][nt][2], acc[mt][nt][3],
                             afr[mt][0], afr[mt][1], afr[mt][2], afr[mt][3],
                             bfr[nt][0], bfr[nt][1]);
        }
    }

    float2 bias2[4];
    #pragma unroll
    for (int nt = 0; nt < 4; nt++)
        bias2[nt] = *(const float2*)(bias + bx * 128 + wn + nt * 8 + tig * 2);

    #pragma unroll
    for (int mt = 0; mt < 4; mt++) {
        const int row = by * 128 + wm + mt * 16 + grp;
        #pragma unroll
        for (int nt = 0; nt < 4; nt++) {
            const int col = bx * 128 + wn + nt * 8 + tig * 2;
            float2 v0, v1;
            v0.x = acc[mt][nt][0] + bias2[nt].x;
            v0.y = acc[mt][nt][1] + bias2[nt].y;
            v1.x = acc[mt][nt][2] + bias2[nt].x;
            v1.y = acc[mt][nt][3] + bias2[nt].y;
            if (round_c) {
                v0.x = f32_to_tf32(v0.x);  v0.y = f32_to_tf32(v0.y);
                v1.x = f32_to_tf32(v1.x);  v1.y = f32_to_tf32(v1.y);
            }
            *(float2*)(C + (size_t)row * N + col)       = v0;
            *(float2*)(C + (size_t)(row + 8) * N + col) = v1;
        }
    }
}

// Fused Q/K/V projection: blockIdx.z selects (input, W, bias, dst).
__global__ void __launch_bounds__(256, 2) mma_gemm_qkv_kernel(
    const float* __restrict__ q, const float* __restrict__ k,
    const float* __restrict__ v,
    const float* __restrict__ Wq, const float* __restrict__ Wk,
    const float* __restrict__ Wv,
    const float* __restrict__ bq, const float* __restrict__ bk,
    const float* __restrict__ bv)
{
    const int z = blockIdx.z;
    const float* A    = (z == 0) ? q  : (z == 1) ? k  : v;
    const float* W    = (z == 0) ? Wq : (z == 1) ? Wk : Wv;
    const float* bias = (z == 0) ? bq : (z == 1) ? bk : bv;
    float* C          = (z == 0) ? g_Qp : (z == 1) ? g_Kp : g_Vp;
    gemm_body(A, W, bias, C, blockIdx.x, blockIdx.y, true);   // pre-rounded
}

// Output projection: reads g_At, writes external out (NOT rounded).
__global__ void __launch_bounds__(256, 2) mma_gemm_out_kernel(
    const float* __restrict__ W, const float* __restrict__ bias,
    float* __restrict__ out)
{
    gemm_body(g_At, W, bias, out, blockIdx.x, blockIdx.y, false);
}

// ============================================================================
// V transpose: g_Vt[b][dg][s] = g_Vp[b][s][dg]   (bit-exact copy)
// ============================================================================
__global__ void __launch_bounds__(256) v_transpose_kernel()
{
    __shared__ float t[32][33];
    const int tx = threadIdx.x, ty = threadIdx.y;   // 32 x 8
    const int s0 = blockIdx.x * 32;
    const int d0 = blockIdx.y * 32;
    const int b  = blockIdx.z;
    const float* src = g_Vp + ((size_t)b * S_LEN) * D_MODEL;
    #pragma unroll
    for (int j = 0; j < 32; j += 8)
        t[ty + j][tx] = src[(size_t)(s0 + ty + j) * D_MODEL + d0 + tx];
    __syncthreads();
    float* dst = g_Vt + ((size_t)b * D_MODEL) * S_LEN;
    #pragma unroll
    for (int j = 0; j < 32; j += 8)
        dst[(size_t)(d0 + ty + j) * S_LEN + s0 + tx] = t[tx][ty + j];
}

// ============================================================================
// Flash attention, mma.sync tf32, cp.async double-buffered K/V, ldmatrix.x4
// fragment loads (causal). Block = (128 q-rows, head, batch), 8 warps.
// K stored [key][dim]; V staged from g_Vt as [dim][key] -> both match the
// ldmatrix B-pattern. P A-frags via ldmatrix too. 72 ldmatrix replace 288 LDS.
// ============================================================================
#define FA3_STR 68
#define FA3_KV  (64 * FA3_STR)
#define FA3_SMEM_BYTES ((4 * FA3_KV + 128 * FA3_STR) * 4)   // 104448 B

__global__ void __launch_bounds__(256, 2) flash_attn_mma_kernel(
    const float* __restrict__ mask)
{
    extern __shared__ float sm[];
    // layout: K0 | V0 | K1 | V1 | P
    float* Ps = sm + 4 * FA3_KV;
    const uint32_t smbase = (uint32_t)__cvta_generic_to_shared(sm);

    const int qt  = (int)gridDim.x - 1 - (int)blockIdx.x;  // heavy tiles first
    const int h   = blockIdx.y;
    const int b   = blockIdx.z;
    const int tid = threadIdx.x;
    const int wid = tid >> 5, lane = tid & 31;
    const int grp = lane >> 2, tig = lane & 3;
    const int wrow = wid * 16;

    // ldmatrix lane->address offsets (bytes)
    const int m_ = lane >> 3, r_ = lane & 7;
    const uint32_t lodB = (uint32_t)(((((m_ >> 1) * 8) + r_) * FA3_STR + (m_ & 1) * 4) * 4);
    const uint32_t lodA = (uint32_t)(((((m_ & 1) * 8) + r_) * FA3_STR + (m_ >> 1) * 4) * 4);

    const size_t base = ((size_t)b * S_LEN) * D_MODEL + h * HDIM;
    const float* mrow = mask + (size_t)b * S_LEN;

    // per-thread staging slots (row lr, 16-float col block lc)
    const int lr = tid >> 2;            // 0..63
    const int lc = (tid & 3) * 16;
    const float* kgbase = g_Kp + base + (size_t)lr * D_MODEL + lc;          // K: row=key
    const float* vgbase = g_Vt + ((size_t)b * D_MODEL + h * HDIM + lr) * S_LEN + lc;  // Vt: row=dim
    const uint32_t kslot = smbase + (uint32_t)((lr * FA3_STR + lc) * 4);
    const uint32_t vslot = kslot + (uint32_t)(FA3_KV * 4);

    // ---- Q fragments in registers (g_Qp already tf32-rounded) ----
    uint32_t qa[8][4];
    {
        const float* Qg = g_Qp + base + (size_t)(qt * 128 + wrow) * D_MODEL;
        #pragma unroll
        for (int ks = 0; ks < 8; ks++) {
            qa[ks][0] = __float_as_uint(Qg[(size_t)grp       * D_MODEL + ks * 8 + tig]);
            qa[ks][1] = __float_as_uint(Qg[(size_t)(grp + 8) * D_MODEL + ks * 8 + tig]);
            qa[ks][2] = __float_as_uint(Qg[(size_t)grp       * D_MODEL + ks * 8 + tig + 4]);
            qa[ks][3] = __float_as_uint(Qg[(size_t)(grp + 8) * D_MODEL + ks * 8 + tig + 4]);
        }
    }

    float Oacc[8][4];
    #pragma unroll
    for (int nt = 0; nt < 8; nt++)
        #pragma unroll
        for (int c = 0; c < 4; c++) Oacc[nt][c] = 0.f;
    float m_run[2] = {-1e30f, -1e30f};
    float l_run[2] = {0.f, 0.f};

    const int qg0 = qt * 128 + wrow + grp;   // row for u=0 (u=1: +8)
    const int ntiles = 2 * qt + 2;

    // prologue: tile 0 into buffer 0
    #pragma unroll
    for (int j = 0; j < 4; j++) {
        CP_ASYNC16(kslot + 16 * j, kgbase + 4 * j);
        CP_ASYNC16(vslot + 16 * j, vgbase + 4 * j);
    }
    CP_COMMIT();

    for (int kt = 0; kt < ntiles; kt++) {
        const int cur = kt & 1;
        CP_WAIT0();
        __syncthreads();

        if (kt + 1 < ntiles) {
            const uint32_t off = (uint32_t)((1 - cur) * 2 * FA3_KV * 4);
            const float* ksn = kgbase + (size_t)(kt + 1) * 64 * D_MODEL;   // keys advance rows
            const float* vsn = vgbase + (size_t)(kt + 1) * 64;             // keys advance cols (Vt)
            #pragma unroll
            for (int j = 0; j < 4; j++) {
                CP_ASYNC16(kslot + off + 16 * j, ksn + 4 * j);
                CP_ASYNC16(vslot + off + 16 * j, vsn + 4 * j);
            }
            CP_COMMIT();
        }

        const uint32_t Kua = smbase + (uint32_t)(cur * 2 * FA3_KV * 4);
        const uint32_t Vua = Kua + (uint32_t)(FA3_KV * 4);

        // ---- scores S = Q @ K^T ----
        float sacc[8][4];
        #pragma unroll
        for (int nt = 0; nt < 8; nt++)
            #pragma unroll
            for (int c = 0; c < 4; c++) sacc[nt][c] = 0.f;

        #pragma unroll
        for (int ks = 0; ks < 8; ks++) {
            #pragma unroll
            for (int ntp = 0; ntp < 4; ntp++) {
                uint32_t b0, b1, b2, b3;
                LDMATRIX_X4(b0, b1, b2, b3,
                            Kua + (uint32_t)(ntp * 16 * FA3_STR * 4 + ks * 32) + lodB);
                mma16888(sacc[2*ntp][0], sacc[2*ntp][1], sacc[2*ntp][2], sacc[2*ntp][3],
                         qa[ks][0], qa[ks][1], qa[ks][2], qa[ks][3], b0, b1);
                mma16888(sacc[2*ntp+1][0], sacc[2*ntp+1][1], sacc[2*ntp+1][2], sacc[2*ntp+1][3],
                         qa[ks][0], qa[ks][1], qa[ks][2], qa[ks][3], b2, b3);
            }
        }

        __syncwarp();   // prior iteration's PV reads of Ps complete

        // ---- online softmax (2 rows/thread) ----
        #pragma unroll
        for (int u = 0; u < 2; u++) {
            const int qg = qg0 + 8 * u;
            float mx = -1e30f;
            #pragma unroll
            for (int nt = 0; nt < 8; nt++) {
                const int kg = kt * 64 + nt * 8 + 2 * tig;
                float2 mv = *(const float2*)(mrow + kg);
                float s0 = sacc[nt][2 * u]     * 0.125f + mv.x;
                float s1 = sacc[nt][2 * u + 1] * 0.125f + mv.y;
                s0 = (kg     <= qg) ? s0 : -1e30f;
                s1 = (kg + 1 <= qg) ? s1 : -1e30f;
                sacc[nt][2 * u]     = s0;
                sacc[nt][2 * u + 1] = s1;
                mx = fmaxf(mx, fmaxf(s0, s1));
            }
            mx = fmaxf(mx, __shfl_xor_sync(0xffffffffu, mx, 1));
            mx = fmaxf(mx, __shfl_xor_sync(0xffffffffu, mx, 2));
            const float m_new = fmaxf(m_run[u], mx);

            float lsum = 0.f;
            #pragma unroll
            for (int nt = 0; nt < 8; nt++) {
                float p0 = __expf(sacc[nt][2 * u]     - m_new);
                float p1 = __expf(sacc[nt][2 * u + 1] - m_new);
                lsum += p0 + p1;
                float2 pr;
                pr.x = f32_to_tf32(p0);
                pr.y = f32_to_tf32(p1);
                *(float2*)(Ps + (wrow + grp + 8 * u) * FA3_STR + nt * 8 + 2 * tig) = pr;
            }
            lsum += __shfl_xor_sync(0xffffffffu, lsum, 1);
            lsum += __shfl_xor_sync(0xffffffffu, lsum, 2);

            const float alpha = __expf(m_run[u] - m_new);
            l_run[u] = l_run[u] * alpha + lsum;
            m_run[u] = m_new;
            #pragma unroll
            for (int nt = 0; nt < 8; nt++) {
                Oacc[nt][2 * u]     *= alpha;
                Oacc[nt][2 * u + 1] *= alpha;
            }
        }
        __syncwarp();   // P stores visible to this warp's fragment loads

        // ---- O += P @ V ----
        const uint32_t Pua = smbase + (uint32_t)(4 * FA3_KV * 4)
                           + (uint32_t)(wrow * FA3_STR * 4);
        #pragma unroll
        for (int ks = 0; ks < 8; ks++) {
            uint32_t pa0, pa1, pa2, pa3;
            LDMATRIX_X4(pa0, pa1, pa2, pa3, Pua + (uint32_t)(ks * 32) + lodA);
            #pragma unroll
            for (int ntp = 0; ntp < 4; ntp++) {
                uint32_t v0, v1, v2, v3;
                LDMATRIX_X4(v0, v1, v2, v3,
                            Vua + (uint32_t)(ntp * 16 * FA3_STR * 4 + ks * 32) + lodB);
                mma16888(Oacc[2*ntp][0], Oacc[2*ntp][1], Oacc[2*ntp][2], Oacc[2*ntp][3],
                         pa0, pa1, pa2, pa3, v0, v1);
                mma16888(Oacc[2*ntp+1][0], Oacc[2*ntp+1][1], Oacc[2*ntp+1][2], Oacc[2*ntp+1][3],
                         pa0, pa1, pa2, pa3, v2, v3);
            }
        }
    }

    // ---- normalize and write out ----
    #pragma unroll
    for (int u = 0; u < 2; u++) {
        const float inv = 1.f / l_run[u];
        float* dst = g_At + base + (size_t)(qg0 + 8 * u) * D_MODEL;
        #pragma unroll
        for (int nt = 0; nt < 8; nt++) {
            float2 o;
            o.x = Oacc[nt][2 * u]     * inv;
            o.y = Oacc[nt][2 * u + 1] * inv;
            *(float2*)(dst + nt * 8 + 2 * tig) = o;
        }
    }
}

// ============================================================================
// Launch
// ============================================================================
extern "C" void kernel_launch(void* const* d_in, const int* in_sizes, int n_in,
                              void* d_out, int out_size)
{
    const float* q    = (const float*)d_in[0];
    const float* k    = (const float*)d_in[1];
    const float* v    = (const float*)d_in[2];
    const float* mask = (const float*)d_in[3];
    const float* Wq   = (const float*)d_in[4];
    const float* bq   = (const float*)d_in[5];
    const float* Wk   = (const float*)d_in[6];
    const float* bk   = (const float*)d_in[7];
    const float* Wv   = (const float*)d_in[8];
    const float* bv   = (const float*)d_in[9];
    const float* Wp   = (const float*)d_in[10];
    const float* bp   = (const float*)d_in[11];
    float* out = (float*)d_out;

    cudaFuncSetAttribute(flash_attn_mma_kernel,
                         cudaFuncAttributeMaxDynamicSharedMemorySize, FA3_SMEM_BYTES);

    dim3 gqkv(D_MODEL / 128, MROWS / 128, 3);     // (8, 64, 3) fused QKV
    mma_gemm_qkv_kernel<<<gqkv, 256>>>(q, k, v, Wq, Wk, Wv, bq, bk, bv);

    dim3 tvb(32, 8), tvg(S_LEN / 32, D_MODEL / 32, BATCH);   // V transpose
    v_transpose_kernel<<<tvg, tvb>>>();

    dim3 fa_grid(S_LEN / 128, NHEAD, BATCH);      // (16, 16, 4)
    flash_attn_mma_kernel<<<fa_grid, 256, FA3_SMEM_BYTES>>>(mask);

    dim3 gg(D_MODEL / 128, MROWS / 128);          // (8, 64)
    mma_gemm_out_kernel<<<gg, 256>>>(Wp, bp, out);
}